// round 9
// baseline (speedup 1.0000x reference)
#include <cuda_runtime.h>
#include <cuda_fp16.h>
#include <cstdint>

// Problem constants (fixed shapes)
#define B_    240
#define S_    64
#define H_    768
#define NH_   12
#define HD_   64
#define L0_   384
#define L1_   128
#define LT_   576          // L0+L1+S
#define BS_   8            // cache0 batch = 240/30
#define OUTSZ (B_*S_*H_)   // 11796480

// scratch for q in [B, nh, S, hd] layout (fp32)
__device__ float g_q[B_ * NH_ * S_ * HD_];

// ---------------------------------------------------------------------------
// helpers
// ---------------------------------------------------------------------------
__device__ __forceinline__ uint32_t packh2(float lo, float hi) {
    __half2 h = __floats2half2_rn(lo, hi);     // .x = lo (low 16 bits)
    return *reinterpret_cast<uint32_t*>(&h);
}

// D(16x8,f32) += A(16x16,f16) * B(16x8,f16)
__device__ __forceinline__ void mma16(float* d, const uint32_t* a, const uint32_t* b) {
    asm volatile(
        "mma.sync.aligned.m16n8k16.row.col.f32.f16.f16.f32 "
        "{%0,%1,%2,%3}, {%4,%5,%6,%7}, {%8,%9}, {%0,%1,%2,%3};"
        : "+f"(d[0]), "+f"(d[1]), "+f"(d[2]), "+f"(d[3])
        : "r"(a[0]), "r"(a[1]), "r"(a[2]), "r"(a[3]), "r"(b[0]), "r"(b[1]));
}

// ===========================================================================
// Kernel 1: QKV projection via fp16 m16n8k16 mma.sync. (unchanged from R8)
// ===========================================================================
#define QW 36   // 32 data u32 (64 halves) + 4 pad: frag LDS conflict-free

__global__ __launch_bounds__(256, 2) void qkv_mma_kernel(
    const float* __restrict__ hidden,
    const float* __restrict__ Wq, const float* __restrict__ bq,
    const float* __restrict__ Wk, const float* __restrict__ bk,
    const float* __restrict__ Wv, const float* __restrict__ bv,
    float* __restrict__ kout, float* __restrict__ vout)
{
    __shared__ uint32_t sA[128 * QW];
    __shared__ uint32_t sB[128 * QW];

    const int tid = threadIdx.x, lane = tid & 31, warp = tid >> 5;
    const int gid = lane >> 2, tig = lane & 3;
    const int nt = blockIdx.x, mt = blockIdx.y, sel = blockIdx.z;

    const float* W    = (sel == 0) ? Wq : (sel == 1) ? Wk : Wv;
    const float* bias = (sel == 0) ? bq : (sel == 1) ? bk : bv;
    float* dst        = (sel == 0) ? g_q : (sel == 1) ? kout : vout;

    const int m0 = mt * 128, n0 = nt * 128;
    const int wm = (warp >> 2) * 64, wn = (warp & 3) * 32;

    float acc[4][4][4];
#pragma unroll
    for (int mi = 0; mi < 4; mi++)
#pragma unroll
        for (int ni = 0; ni < 4; ni++)
#pragma unroll
            for (int j = 0; j < 4; j++) acc[mi][ni][j] = 0.f;

    for (int i = 0; i < 12; i++) {
        const int k0 = i * 64;
        __syncthreads();
        {
            float4 va[8];
#pragma unroll
            for (int p = 0; p < 4; p++) {
                int g = p * 256 + tid;
                const float* src = hidden + (size_t)(m0 + (g >> 3)) * H_ + k0 + (g & 7) * 8;
                va[2*p]   = *(const float4*)(src);
                va[2*p+1] = *(const float4*)(src + 4);
            }
#pragma unroll
            for (int p = 0; p < 4; p++) {
                int g = p * 256 + tid;
                uint4 t;
                t.x = packh2(va[2*p].x,   va[2*p].y);
                t.y = packh2(va[2*p].z,   va[2*p].w);
                t.z = packh2(va[2*p+1].x, va[2*p+1].y);
                t.w = packh2(va[2*p+1].z, va[2*p+1].w);
                *(uint4*)&sA[(g >> 3) * QW + (g & 7) * 4] = t;
            }
#pragma unroll
            for (int p = 0; p < 4; p++) {
                int g = p * 256 + tid;
                const float* src = W + (size_t)(n0 + (g >> 3)) * H_ + k0 + (g & 7) * 8;
                va[2*p]   = *(const float4*)(src);
                va[2*p+1] = *(const float4*)(src + 4);
            }
#pragma unroll
            for (int p = 0; p < 4; p++) {
                int g = p * 256 + tid;
                uint4 t;
                t.x = packh2(va[2*p].x,   va[2*p].y);
                t.y = packh2(va[2*p].z,   va[2*p].w);
                t.z = packh2(va[2*p+1].x, va[2*p+1].y);
                t.w = packh2(va[2*p+1].z, va[2*p+1].w);
                *(uint4*)&sB[(g >> 3) * QW + (g & 7) * 4] = t;
            }
        }
        __syncthreads();

#pragma unroll
        for (int kg = 0; kg < 4; kg++) {
            const int c0 = kg * 8 + tig;
            uint32_t a[4][4], bf[4][2];
#pragma unroll
            for (int mi = 0; mi < 4; mi++) {
                int r = wm + mi * 16 + gid;
                a[mi][0] = sA[r * QW + c0];
                a[mi][1] = sA[(r + 8) * QW + c0];
                a[mi][2] = sA[r * QW + c0 + 4];
                a[mi][3] = sA[(r + 8) * QW + c0 + 4];
            }
#pragma unroll
            for (int ni = 0; ni < 4; ni++) {
                int rn = wn + ni * 8 + gid;
                bf[ni][0] = sB[rn * QW + c0];
                bf[ni][1] = sB[rn * QW + c0 + 4];
            }
#pragma unroll
            for (int mi = 0; mi < 4; mi++)
#pragma unroll
                for (int ni = 0; ni < 4; ni++)
                    mma16(acc[mi][ni], a[mi], bf[ni]);
        }
    }

#pragma unroll
    for (int ni = 0; ni < 4; ni++) {
        int gn = n0 + wn + ni * 8 + 2 * tig;
        float b0 = __ldg(bias + gn), b1 = __ldg(bias + gn + 1);
        int hh = gn >> 6, dd = gn & 63;
#pragma unroll
        for (int mi = 0; mi < 4; mi++) {
            int gm = m0 + wm + mi * 16 + gid;
            int bb = gm >> 6, ss = gm & 63;
            float2 v0 = { acc[mi][ni][0] + b0, acc[mi][ni][1] + b1 };
            *(float2*)(dst + (((size_t)bb * NH_ + hh) * S_ + ss) * HD_ + dd) = v0;
            int gm2 = gm + 8;
            bb = gm2 >> 6; ss = gm2 & 63;
            float2 v1 = { acc[mi][ni][2] + b0, acc[mi][ni][3] + b1 };
            *(float2*)(dst + (((size_t)bb * NH_ + hh) * S_ + ss) * HD_ + dd) = v1;
        }
    }
}

// ===========================================================================
// Kernel 2: attention, fp16 m16n8k16 + online softmax.
// R9: double-buffered K/V (1 sync/tile), Q frags reloaded from smem,
// __launch_bounds__(128,5) to pin 5 CTAs/SM.
// ===========================================================================
#define KW 36   // 32 data u32 + 4 pad (qs, ks rows)
#define VW 20   // 16 data u32 + 4 pad (vsT rows)
#define NTILE 18   // 12 (L0) + 4 (L1) + 2 (self)

__global__ __launch_bounds__(128, 5) void attn_mma_kernel(
    const float* __restrict__ kout, const float* __restrict__ vout,
    const float* __restrict__ c0k,  const float* __restrict__ c0v,
    const float* __restrict__ c1k,  const float* __restrict__ c1v,
    const float* __restrict__ mask, float* __restrict__ out)
{
    __shared__ uint32_t qs[64 * KW];          // Q: 64 rows x 64 halves
    __shared__ uint32_t ks[2][32 * KW];       // K double buffer
    __shared__ uint32_t vsT[2][64 * VW];      // V^T double buffer
    __shared__ float msm[2][32];

    const unsigned FULL = 0xffffffffu;
    const int bh = blockIdx.x, b = bh / NH_, h = bh % NH_;
    const int tid = threadIdx.x, lane = tid & 31, warp = tid >> 5;
    const int gid = lane >> 2, tig = lane & 3;
    const int rQ = warp * 16 + gid;
    const int kp = tid & 15, dg = tid >> 4;   // V-transpose staging coords
    const float* maskb = mask + (size_t)b * LT_;

    // segment tables
    const float* segK[3];
    const float* segV[3];
    {
        size_t o0 = ((size_t)(b % BS_) * NH_ + h) * L0_ * HD_;
        size_t o1 = ((size_t)b * NH_ + h) * L1_ * HD_;
        size_t o2 = ((size_t)b * NH_ + h) * S_ * HD_;
        segK[0] = c0k + o0;  segV[0] = c0v + o0;
        segK[1] = c1k + o1;  segV[1] = c1v + o1;
        segK[2] = kout + o2; segV[2] = vout + o2;
    }

    auto stage = [&](int j, int bufi) {
        int seg = (j >= 16) ? 2 : (j >= 12) ? 1 : 0;
        int segbase = (seg == 2) ? 512 : (seg == 1) ? 384 : 0;
        const float* kb = segK[seg] + (size_t)(j * 32 - segbase) * HD_;
        const float* vb = segV[seg] + (size_t)(j * 32 - segbase) * HD_;
        uint32_t* ksb = &ks[bufi][0];
        uint32_t* vtb = &vsT[bufi][0];
#pragma unroll
        for (int p = 0; p < 4; p++) {
            int idx = p * 128 + tid;
            int r = idx >> 4, c4 = idx & 15;
            float4 kv = *(const float4*)(kb + (size_t)r * HD_ + c4 * 4);
            uint2 tk = { packh2(kv.x, kv.y), packh2(kv.z, kv.w) };
            *(uint2*)&ksb[r * KW + c4 * 2] = tk;
        }
        {
            const float* v0 = vb + (size_t)(2 * kp) * HD_ + dg * 8;
            const float* v1 = v0 + HD_;
            float4 a0 = *(const float4*)(v0);
            float4 a1 = *(const float4*)(v0 + 4);
            float4 b0 = *(const float4*)(v1);
            float4 b1 = *(const float4*)(v1 + 4);
            int dbase = dg * 8;
            vtb[(dbase + 0) * VW + kp] = packh2(a0.x, b0.x);
            vtb[(dbase + 1) * VW + kp] = packh2(a0.y, b0.y);
            vtb[(dbase + 2) * VW + kp] = packh2(a0.z, b0.z);
            vtb[(dbase + 3) * VW + kp] = packh2(a0.w, b0.w);
            vtb[(dbase + 4) * VW + kp] = packh2(a1.x, b1.x);
            vtb[(dbase + 5) * VW + kp] = packh2(a1.y, b1.y);
            vtb[(dbase + 6) * VW + kp] = packh2(a1.z, b1.z);
            vtb[(dbase + 7) * VW + kp] = packh2(a1.w, b1.w);
        }
        if (tid < 32) msm[bufi][tid] = maskb[j * 32 + tid];
    };

    // stage Q (pre-scaled by 1/8) as packed fp16 + stage tile 0
    {
        const float* qp = g_q + (size_t)bh * S_ * HD_;
#pragma unroll
        for (int p = 0; p < 8; p++) {
            int idx = p * 128 + tid;
            int r = idx >> 4, c4 = idx & 15;
            float4 v = *(const float4*)(qp + r * HD_ + c4 * 4);
            uint2 t = { packh2(v.x * 0.125f, v.y * 0.125f),
                        packh2(v.z * 0.125f, v.w * 0.125f) };
            *(uint2*)&qs[r * KW + c4 * 2] = t;
        }
    }
    stage(0, 0);
    __syncthreads();

    float o[8][4];
#pragma unroll
    for (int nd = 0; nd < 8; nd++)
#pragma unroll
        for (int j = 0; j < 4; j++) o[nd][j] = 0.f;
    float m0 = -1e30f, m1 = -1e30f, l0 = 0.f, l1 = 0.f;

    for (int j = 0; j < NTILE; j++) {
        const int bufi = j & 1;
        const uint32_t* ksb = &ks[bufi][0];
        const uint32_t* vtb = &vsT[bufi][0];
        const float* msb = &msm[bufi][0];

        // scores: kk outer (qf loaded once), nb inner
        float sc[4][4];
#pragma unroll
        for (int nb = 0; nb < 4; nb++)
            sc[nb][0] = sc[nb][1] = sc[nb][2] = sc[nb][3] = 0.f;
#pragma unroll
        for (int kk = 0; kk < 4; kk++) {
            const int c = kk * 8 + tig;
            uint32_t qfk[4];
            qfk[0] = qs[rQ * KW + c];
            qfk[1] = qs[(rQ + 8) * KW + c];
            qfk[2] = qs[rQ * KW + c + 4];
            qfk[3] = qs[(rQ + 8) * KW + c + 4];
#pragma unroll
            for (int nb = 0; nb < 4; nb++) {
                uint32_t bf[2];
                int rn = nb * 8 + gid;
                bf[0] = ksb[rn * KW + c];
                bf[1] = ksb[rn * KW + c + 4];
                mma16(sc[nb], qfk, bf);
            }
        }
#pragma unroll
        for (int nb = 0; nb < 4; nb++) {
            float mk0 = msb[nb * 8 + 2 * tig], mk1 = msb[nb * 8 + 2 * tig + 1];
            sc[nb][0] += mk0; sc[nb][1] += mk1;
            sc[nb][2] += mk0; sc[nb][3] += mk1;
        }

        // online softmax (rows rQ and rQ+8)
        float tm0 = -1e30f, tm1 = -1e30f;
#pragma unroll
        for (int nb = 0; nb < 4; nb++) {
            tm0 = fmaxf(tm0, fmaxf(sc[nb][0], sc[nb][1]));
            tm1 = fmaxf(tm1, fmaxf(sc[nb][2], sc[nb][3]));
        }
        tm0 = fmaxf(tm0, __shfl_xor_sync(FULL, tm0, 1));
        tm0 = fmaxf(tm0, __shfl_xor_sync(FULL, tm0, 2));
        tm1 = fmaxf(tm1, __shfl_xor_sync(FULL, tm1, 1));
        tm1 = fmaxf(tm1, __shfl_xor_sync(FULL, tm1, 2));
        float nm0 = fmaxf(m0, tm0), nm1 = fmaxf(m1, tm1);
        float cr0 = __expf(m0 - nm0), cr1 = __expf(m1 - nm1);
        m0 = nm0; m1 = nm1;
        l0 *= cr0; l1 *= cr1;

        // exp + pack P directly into k16 A-fragments
        uint32_t pa[2][4];
#pragma unroll
        for (int kc = 0; kc < 2; kc++) {
            float p00 = __expf(sc[2*kc][0]   - m0), p01 = __expf(sc[2*kc][1]   - m0);
            float p02 = __expf(sc[2*kc][2]   - m1), p03 = __expf(sc[2*kc][3]   - m1);
            float p10 = __expf(sc[2*kc+1][0] - m0), p11 = __expf(sc[2*kc+1][1] - m0);
            float p12 = __expf(sc[2*kc+1][2] - m1), p13 = __expf(sc[2*kc+1][3] - m1);
            l0 += p00 + p01 + p10 + p11;
            l1 += p02 + p03 + p12 + p13;
            pa[kc][0] = packh2(p00, p01);
            pa[kc][1] = packh2(p02, p03);
            pa[kc][2] = packh2(p10, p11);
            pa[kc][3] = packh2(p12, p13);
        }
#pragma unroll
        for (int nd = 0; nd < 8; nd++) {
            o[nd][0] *= cr0; o[nd][1] *= cr0;
            o[nd][2] *= cr1; o[nd][3] *= cr1;
        }

        // P @ V : 2 k16 groups x 8 dim-blocks
#pragma unroll
        for (int kc = 0; kc < 2; kc++) {
#pragma unroll
            for (int nd = 0; nd < 8; nd++) {
                uint32_t vf[2];
                int rd = nd * 8 + gid, c = kc * 8 + tig;
                vf[0] = vtb[rd * VW + c];
                vf[1] = vtb[rd * VW + c + 4];
                mma16(o[nd], pa[kc], vf);
            }
        }

        // stage next tile into the other buffer, then one barrier
        if (j + 1 < NTILE) stage(j + 1, (j + 1) & 1);
        __syncthreads();
    }

    l0 += __shfl_xor_sync(FULL, l0, 1);
    l0 += __shfl_xor_sync(FULL, l0, 2);
    l1 += __shfl_xor_sync(FULL, l1, 1);
    l1 += __shfl_xor_sync(FULL, l1, 2);
    float i0 = 1.f / l0, i1 = 1.f / l1;

    const int s = warp * 16 + gid;
    float* ob  = out + ((size_t)b * S_ + s) * H_ + h * HD_;
    float* ob2 = out + ((size_t)b * S_ + s + 8) * H_ + h * HD_;
#pragma unroll
    for (int nd = 0; nd < 8; nd++) {
        int d = nd * 8 + 2 * tig;
        float2 v0 = { o[nd][0] * i0, o[nd][1] * i0 };
        float2 v1 = { o[nd][2] * i1, o[nd][3] * i1 };
        *(float2*)(ob + d)  = v0;
        *(float2*)(ob2 + d) = v1;
    }
}

// ---------------------------------------------------------------------------
extern "C" void kernel_launch(void* const* d_in, const int* in_sizes, int n_in,
                              void* d_out, int out_size)
{
    const float* hidden = (const float*)d_in[0];
    const float* mask   = (const float*)d_in[1];
    const float* Wq     = (const float*)d_in[2];
    const float* bq     = (const float*)d_in[3];
    const float* Wk     = (const float*)d_in[4];
    const float* bk     = (const float*)d_in[5];
    const float* Wv     = (const float*)d_in[6];
    const float* bv     = (const float*)d_in[7];
    const float* c0k    = (const float*)d_in[8];
    const float* c0v    = (const float*)d_in[9];
    const float* c1k    = (const float*)d_in[10];
    const float* c1v    = (const float*)d_in[11];

    float* out  = (float*)d_out;
    float* kout = out + (size_t)OUTSZ;
    float* vout = out + (size_t)2 * OUTSZ;

    dim3 g1(6, 120, 3);
    qkv_mma_kernel<<<g1, 256>>>(hidden, Wq, bq, Wk, bk, Wv, bv, kout, vout);

    attn_mma_kernel<<<B_ * NH_, 128>>>(kout, vout, c0k, c0v, c1k, c1v, mask, out);
}

// round 10
// speedup vs baseline: 1.1730x; 1.1730x over previous
#include <cuda_runtime.h>
#include <cuda_fp16.h>
#include <cstdint>

// Problem constants (fixed shapes)
#define B_    240
#define S_    64
#define H_    768
#define NH_   12
#define HD_   64
#define L0_   384
#define L1_   128
#define LT_   576          // L0+L1+S
#define BS_   8            // cache0 batch = 240/30
#define OUTSZ (B_*S_*H_)   // 11796480

// scratch for q in [B, nh, S, hd] layout (fp32)
__device__ float g_q[B_ * NH_ * S_ * HD_];

// ---------------------------------------------------------------------------
// helpers
// ---------------------------------------------------------------------------
__device__ __forceinline__ uint32_t packh2(float lo, float hi) {
    __half2 h = __floats2half2_rn(lo, hi);     // .x = lo (low 16 bits)
    return *reinterpret_cast<uint32_t*>(&h);
}
__device__ __forceinline__ uint32_t smem_u32(const void* p) {
    uint32_t a;
    asm("{ .reg .u64 t; cvta.to.shared.u64 t, %1; cvt.u32.u64 %0, t; }"
        : "=r"(a) : "l"(p));
    return a;
}
// D(16x8,f32) += A(16x16,f16) * B(16x8,f16)
__device__ __forceinline__ void mma16(float* d, const uint32_t* a, const uint32_t* b) {
    asm volatile(
        "mma.sync.aligned.m16n8k16.row.col.f32.f16.f16.f32 "
        "{%0,%1,%2,%3}, {%4,%5,%6,%7}, {%8,%9}, {%0,%1,%2,%3};"
        : "+f"(d[0]), "+f"(d[1]), "+f"(d[2]), "+f"(d[3])
        : "r"(a[0]), "r"(a[1]), "r"(a[2]), "r"(a[3]), "r"(b[0]), "r"(b[1]));
}
// load 4 8x8 b16 matrices; matrix i row addrs from lanes 8i..8i+7
__device__ __forceinline__ void ldsm4(uint32_t* d, uint32_t addr) {
    asm volatile("ldmatrix.sync.aligned.m8n8.x4.shared.b16 {%0,%1,%2,%3}, [%4];"
        : "=r"(d[0]), "=r"(d[1]), "=r"(d[2]), "=r"(d[3]) : "r"(addr));
}

// ===========================================================================
// Kernel 1: QKV projection via fp16 m16n8k16 mma.sync + ldmatrix fragments.
// C[15360,768] = hidden @ W^T + bias -> [B, nh, S, hd] layout.
// 128x128 CTA tile, BK=64 (4 k16 groups), 256 thr (8 warps, 64x32 warp tile).
// ===========================================================================
#define QW 36   // 32 data u32 (64 halves) + 4 pad: ldmatrix conflict-free

__global__ __launch_bounds__(256, 2) void qkv_mma_kernel(
    const float* __restrict__ hidden,
    const float* __restrict__ Wq, const float* __restrict__ bq,
    const float* __restrict__ Wk, const float* __restrict__ bk,
    const float* __restrict__ Wv, const float* __restrict__ bv,
    float* __restrict__ kout, float* __restrict__ vout)
{
    __shared__ uint32_t sA[128 * QW];
    __shared__ uint32_t sB[128 * QW];

    const int tid = threadIdx.x, lane = tid & 31, warp = tid >> 5;
    const int gid = lane >> 2, tig = lane & 3;
    const int nt = blockIdx.x, mt = blockIdx.y, sel = blockIdx.z;

    const float* W    = (sel == 0) ? Wq : (sel == 1) ? Wk : Wv;
    const float* bias = (sel == 0) ? bq : (sel == 1) ? bk : bv;
    float* dst        = (sel == 0) ? g_q : (sel == 1) ? kout : vout;

    const int m0 = mt * 128, n0 = nt * 128;
    const int wm = (warp >> 2) * 64, wn = (warp & 3) * 32;

    // per-lane ldmatrix addressing
    const uint32_t sAu = smem_u32(sA), sBu = smem_u32(sB);
    // A: matrices (row-half, k-half): lanes 0-7 -> rows+0 k0 | 8-15 -> rows+8 k0
    //    | 16-23 -> rows+0 k1 | 24-31 -> rows+8 k1
    const int arow = ((lane >> 3) & 1) * 8 + (lane & 7);
    const int acol = (lane >> 4) * 4;
    // B: matrices (ni within pair, k-half): lanes 0-7 -> ni+0 k0 | 8-15 -> ni+0 k1
    //    | 16-23 -> ni+1 k0 | 24-31 -> ni+1 k1
    const int brow = (lane >> 4) * 8 + (lane & 7);
    const int bcol = ((lane >> 3) & 1) * 4;

    float acc[4][4][4];
#pragma unroll
    for (int mi = 0; mi < 4; mi++)
#pragma unroll
        for (int ni = 0; ni < 4; ni++)
#pragma unroll
            for (int j = 0; j < 4; j++) acc[mi][ni][j] = 0.f;

    for (int i = 0; i < 12; i++) {
        const int k0 = i * 64;
        __syncthreads();
        // coalesced staging: group g -> row g>>3, 8 floats at (g&7)*8
        {
            float4 va[8];
#pragma unroll
            for (int p = 0; p < 4; p++) {
                int g = p * 256 + tid;
                const float* src = hidden + (size_t)(m0 + (g >> 3)) * H_ + k0 + (g & 7) * 8;
                va[2*p]   = *(const float4*)(src);
                va[2*p+1] = *(const float4*)(src + 4);
            }
#pragma unroll
            for (int p = 0; p < 4; p++) {
                int g = p * 256 + tid;
                uint4 t;
                t.x = packh2(va[2*p].x,   va[2*p].y);
                t.y = packh2(va[2*p].z,   va[2*p].w);
                t.z = packh2(va[2*p+1].x, va[2*p+1].y);
                t.w = packh2(va[2*p+1].z, va[2*p+1].w);
                *(uint4*)&sA[(g >> 3) * QW + (g & 7) * 4] = t;
            }
#pragma unroll
            for (int p = 0; p < 4; p++) {
                int g = p * 256 + tid;
                const float* src = W + (size_t)(n0 + (g >> 3)) * H_ + k0 + (g & 7) * 8;
                va[2*p]   = *(const float4*)(src);
                va[2*p+1] = *(const float4*)(src + 4);
            }
#pragma unroll
            for (int p = 0; p < 4; p++) {
                int g = p * 256 + tid;
                uint4 t;
                t.x = packh2(va[2*p].x,   va[2*p].y);
                t.y = packh2(va[2*p].z,   va[2*p].w);
                t.z = packh2(va[2*p+1].x, va[2*p+1].y);
                t.w = packh2(va[2*p+1].z, va[2*p+1].w);
                *(uint4*)&sB[(g >> 3) * QW + (g & 7) * 4] = t;
            }
        }
        __syncthreads();

#pragma unroll
        for (int kg = 0; kg < 4; kg++) {
            uint32_t a[4][4], bf[4][2];
#pragma unroll
            for (int mi = 0; mi < 4; mi++) {
                uint32_t addr = sAu + (uint32_t)(((wm + mi * 16 + arow) * QW
                                                  + kg * 8 + acol) * 4);
                ldsm4(a[mi], addr);
            }
#pragma unroll
            for (int j = 0; j < 2; j++) {
                uint32_t d[4];
                uint32_t addr = sBu + (uint32_t)(((wn + j * 16 + brow) * QW
                                                  + kg * 8 + bcol) * 4);
                ldsm4(d, addr);
                bf[2*j][0]   = d[0]; bf[2*j][1]   = d[1];
                bf[2*j+1][0] = d[2]; bf[2*j+1][1] = d[3];
            }
#pragma unroll
            for (int mi = 0; mi < 4; mi++)
#pragma unroll
                for (int ni = 0; ni < 4; ni++)
                    mma16(acc[mi][ni], a[mi], bf[ni]);
        }
    }

    // epilogue: bias + store into [B, nh, S, hd]
#pragma unroll
    for (int ni = 0; ni < 4; ni++) {
        int gn = n0 + wn + ni * 8 + 2 * tig;
        float b0 = __ldg(bias + gn), b1 = __ldg(bias + gn + 1);
        int hh = gn >> 6, dd = gn & 63;
#pragma unroll
        for (int mi = 0; mi < 4; mi++) {
            int gm = m0 + wm + mi * 16 + gid;
            int bb = gm >> 6, ss = gm & 63;
            float2 v0 = { acc[mi][ni][0] + b0, acc[mi][ni][1] + b1 };
            *(float2*)(dst + (((size_t)bb * NH_ + hh) * S_ + ss) * HD_ + dd) = v0;
            int gm2 = gm + 8;
            bb = gm2 >> 6; ss = gm2 & 63;
            float2 v1 = { acc[mi][ni][2] + b0, acc[mi][ni][3] + b1 };
            *(float2*)(dst + (((size_t)bb * NH_ + hh) * S_ + ss) * HD_ + dd) = v1;
        }
    }
}

// ===========================================================================
// Kernel 2: attention via fp16 m16n8k16 mma.sync + online softmax.
// (R8 version verbatim — the 236us control)
// ===========================================================================
#define KW 36   // 32 data u32 + 4 pad (qs, ks rows)
#define VW 20   // 16 data u32 + 4 pad (vsT rows)

__global__ __launch_bounds__(128) void attn_mma_kernel(
    const float* __restrict__ kout, const float* __restrict__ vout,
    const float* __restrict__ c0k,  const float* __restrict__ c0v,
    const float* __restrict__ c1k,  const float* __restrict__ c1v,
    const float* __restrict__ mask, float* __restrict__ out)
{
    __shared__ uint32_t qs[64 * KW];     // Q: 64 rows x 64 halves
    __shared__ uint32_t ks[32 * KW];     // K: 32 keys x 64 halves
    __shared__ uint32_t vsT[64 * VW];    // V^T: 64 dims x 32 halves (keys)
    __shared__ float msm[32];

    const unsigned FULL = 0xffffffffu;
    const int bh = blockIdx.x, b = bh / NH_, h = bh % NH_;
    const int tid = threadIdx.x, lane = tid & 31, warp = tid >> 5;
    const int gid = lane >> 2, tig = lane & 3;

    // stage Q (pre-scaled by 1/8) as packed fp16
    {
        const float* qp = g_q + (size_t)bh * S_ * HD_;
#pragma unroll
        for (int p = 0; p < 8; p++) {
            int idx = p * 128 + tid;
            int r = idx >> 4, c4 = idx & 15;
            float4 v = *(const float4*)(qp + r * HD_ + c4 * 4);
            uint2 t = { packh2(v.x * 0.125f, v.y * 0.125f),
                        packh2(v.z * 0.125f, v.w * 0.125f) };
            *(uint2*)&qs[r * KW + c4 * 2] = t;
        }
    }
    __syncthreads();

    // Q fragments: qf[kk] covers k-dims 16*kk .. 16*kk+15
    uint32_t qf[4][4];
    {
        const int r = warp * 16 + gid;
#pragma unroll
        for (int kk = 0; kk < 4; kk++) {
            int c = kk * 8 + tig;
            qf[kk][0] = qs[r * KW + c];
            qf[kk][1] = qs[(r + 8) * KW + c];
            qf[kk][2] = qs[r * KW + c + 4];
            qf[kk][3] = qs[(r + 8) * KW + c + 4];
        }
    }

    float o[8][4];
#pragma unroll
    for (int nd = 0; nd < 8; nd++)
#pragma unroll
        for (int j = 0; j < 4; j++) o[nd][j] = 0.f;
    float m0 = -1e30f, m1 = -1e30f, l0 = 0.f, l1 = 0.f;

    const float* maskb = mask + (size_t)b * LT_;
    const int kp = tid & 15, dg = tid >> 4;   // V-transpose staging coords

    for (int seg = 0; seg < 3; seg++) {
        const float *kb, *vb;
        int len, posbase;
        if (seg == 0) {
            size_t off = ((size_t)(b % BS_) * NH_ + h) * L0_ * HD_;
            kb = c0k + off; vb = c0v + off; len = L0_; posbase = 0;
        } else if (seg == 1) {
            size_t off = ((size_t)b * NH_ + h) * L1_ * HD_;
            kb = c1k + off; vb = c1v + off; len = L1_; posbase = L0_;
        } else {
            size_t off = ((size_t)b * NH_ + h) * S_ * HD_;
            kb = kout + off; vb = vout + off; len = S_; posbase = L0_ + L1_;
        }

        for (int t = 0; t < len; t += 32) {
            __syncthreads();
            // K: rows = keys, packed along d
#pragma unroll
            for (int p = 0; p < 4; p++) {
                int idx = p * 128 + tid;
                int r = idx >> 4, c4 = idx & 15;
                float4 kv = *(const float4*)(kb + (size_t)(t + r) * HD_ + c4 * 4);
                uint2 tk = { packh2(kv.x, kv.y), packh2(kv.z, kv.w) };
                *(uint2*)&ks[r * KW + c4 * 2] = tk;
            }
            // V transposed: vsT[d][kp] = h2(V[2kp][d], V[2kp+1][d])
            {
                const float* v0 = vb + (size_t)(t + 2 * kp) * HD_ + dg * 8;
                const float* v1 = v0 + HD_;
                float4 a0 = *(const float4*)(v0);
                float4 a1 = *(const float4*)(v0 + 4);
                float4 b0 = *(const float4*)(v1);
                float4 b1 = *(const float4*)(v1 + 4);
                int dbase = dg * 8;
                vsT[(dbase + 0) * VW + kp] = packh2(a0.x, b0.x);
                vsT[(dbase + 1) * VW + kp] = packh2(a0.y, b0.y);
                vsT[(dbase + 2) * VW + kp] = packh2(a0.z, b0.z);
                vsT[(dbase + 3) * VW + kp] = packh2(a0.w, b0.w);
                vsT[(dbase + 4) * VW + kp] = packh2(a1.x, b1.x);
                vsT[(dbase + 5) * VW + kp] = packh2(a1.y, b1.y);
                vsT[(dbase + 6) * VW + kp] = packh2(a1.z, b1.z);
                vsT[(dbase + 7) * VW + kp] = packh2(a1.w, b1.w);
            }
            if (tid < 32) msm[tid] = maskb[posbase + t + tid];
            __syncthreads();

            // scores: S[16 rows][32 keys] per warp (4 n-blocks x 4 k16 groups)
            float sc[4][4];
#pragma unroll
            for (int nb = 0; nb < 4; nb++) {
                sc[nb][0] = sc[nb][1] = sc[nb][2] = sc[nb][3] = 0.f;
#pragma unroll
                for (int kk = 0; kk < 4; kk++) {
                    uint32_t bf[2];
                    int rn = nb * 8 + gid, c = kk * 8 + tig;
                    bf[0] = ks[rn * KW + c];
                    bf[1] = ks[rn * KW + c + 4];
                    mma16(sc[nb], qf[kk], bf);
                }
                float mk0 = msm[nb * 8 + 2 * tig], mk1 = msm[nb * 8 + 2 * tig + 1];
                sc[nb][0] += mk0; sc[nb][1] += mk1;
                sc[nb][2] += mk0; sc[nb][3] += mk1;
            }

            // online softmax (rows r = gid and r+8)
            float tm0 = -1e30f, tm1 = -1e30f;
#pragma unroll
            for (int nb = 0; nb < 4; nb++) {
                tm0 = fmaxf(tm0, fmaxf(sc[nb][0], sc[nb][1]));
                tm1 = fmaxf(tm1, fmaxf(sc[nb][2], sc[nb][3]));
            }
            tm0 = fmaxf(tm0, __shfl_xor_sync(FULL, tm0, 1));
            tm0 = fmaxf(tm0, __shfl_xor_sync(FULL, tm0, 2));
            tm1 = fmaxf(tm1, __shfl_xor_sync(FULL, tm1, 1));
            tm1 = fmaxf(tm1, __shfl_xor_sync(FULL, tm1, 2));
            float nm0 = fmaxf(m0, tm0), nm1 = fmaxf(m1, tm1);
            float cr0 = __expf(m0 - nm0), cr1 = __expf(m1 - nm1);
            m0 = nm0; m1 = nm1;
            l0 *= cr0; l1 *= cr1;

            // exp + pack P directly into k16 A-fragments (no shuffles!)
            uint32_t pa[2][4];
#pragma unroll
            for (int kc = 0; kc < 2; kc++) {
                float p00 = __expf(sc[2*kc][0]   - m0), p01 = __expf(sc[2*kc][1]   - m0);
                float p02 = __expf(sc[2*kc][2]   - m1), p03 = __expf(sc[2*kc][3]   - m1);
                float p10 = __expf(sc[2*kc+1][0] - m0), p11 = __expf(sc[2*kc+1][1] - m0);
                float p12 = __expf(sc[2*kc+1][2] - m1), p13 = __expf(sc[2*kc+1][3] - m1);
                l0 += p00 + p01 + p10 + p11;
                l1 += p02 + p03 + p12 + p13;
                pa[kc][0] = packh2(p00, p01);
                pa[kc][1] = packh2(p02, p03);
                pa[kc][2] = packh2(p10, p11);
                pa[kc][3] = packh2(p12, p13);
            }
#pragma unroll
            for (int nd = 0; nd < 8; nd++) {
                o[nd][0] *= cr0; o[nd][1] *= cr0;
                o[nd][2] *= cr1; o[nd][3] *= cr1;
            }

            // P @ V : 2 k16 groups x 8 dim-blocks
#pragma unroll
            for (int kc = 0; kc < 2; kc++) {
#pragma unroll
                for (int nd = 0; nd < 8; nd++) {
                    uint32_t vf[2];
                    int rd = nd * 8 + gid, c = kc * 8 + tig;
                    vf[0] = vsT[rd * VW + c];
                    vf[1] = vsT[rd * VW + c + 4];
                    mma16(o[nd], pa[kc], vf);
                }
            }
        }
    }

    l0 += __shfl_xor_sync(FULL, l0, 1);
    l0 += __shfl_xor_sync(FULL, l0, 2);
    l1 += __shfl_xor_sync(FULL, l1, 1);
    l1 += __shfl_xor_sync(FULL, l1, 2);
    float i0 = 1.f / l0, i1 = 1.f / l1;

    const int s = warp * 16 + gid;
    float* ob  = out + ((size_t)b * S_ + s) * H_ + h * HD_;
    float* ob2 = out + ((size_t)b * S_ + s + 8) * H_ + h * HD_;
#pragma unroll
    for (int nd = 0; nd < 8; nd++) {
        int d = nd * 8 + 2 * tig;
        float2 v0 = { o[nd][0] * i0, o[nd][1] * i0 };
        float2 v1 = { o[nd][2] * i1, o[nd][3] * i1 };
        *(float2*)(ob + d)  = v0;
        *(float2*)(ob2 + d) = v1;
    }
}

// ---------------------------------------------------------------------------
extern "C" void kernel_launch(void* const* d_in, const int* in_sizes, int n_in,
                              void* d_out, int out_size)
{
    const float* hidden = (const float*)d_in[0];
    const float* mask   = (const float*)d_in[1];
    const float* Wq     = (const float*)d_in[2];
    const float* bq     = (const float*)d_in[3];
    const float* Wk     = (const float*)d_in[4];
    const float* bk     = (const float*)d_in[5];
    const float* Wv     = (const float*)d_in[6];
    const float* bv     = (const float*)d_in[7];
    const float* c0k    = (const float*)d_in[8];
    const float* c0v    = (const float*)d_in[9];
    const float* c1k    = (const float*)d_in[10];
    const float* c1v    = (const float*)d_in[11];

    float* out  = (float*)d_out;
    float* kout = out + (size_t)OUTSZ;
    float* vout = out + (size_t)2 * OUTSZ;

    dim3 g1(6, 120, 3);
    qkv_mma_kernel<<<g1, 256>>>(hidden, Wq, bq, Wk, bk, Wv, bv, kout, vout);

    attn_mma_kernel<<<B_ * NH_, 128>>>(kout, vout, c0k, c0v, c1k, c1v, mask, out);
}

// round 11
// speedup vs baseline: 1.4021x; 1.1953x over previous
#include <cuda_runtime.h>
#include <cuda_fp16.h>
#include <cstdint>

// Problem constants (fixed shapes)
#define B_    240
#define S_    64
#define H_    768
#define NH_   12
#define HD_   64
#define L0_   384
#define L1_   128
#define LT_   576          // L0+L1+S
#define BS_   8            // cache0 batch = 240/30
#define OUTSZ (B_*S_*H_)   // 11796480

// scratch for q in [B, nh, S, hd] layout (fp32)
__device__ float g_q[B_ * NH_ * S_ * HD_];

// ---------------------------------------------------------------------------
// helpers
// ---------------------------------------------------------------------------
__device__ __forceinline__ uint32_t packh2(float lo, float hi) {
    __half2 h = __floats2half2_rn(lo, hi);     // .x = lo (low 16 bits)
    return *reinterpret_cast<uint32_t*>(&h);
}
__device__ __forceinline__ uint32_t smem_u32(const void* p) {
    uint32_t a;
    asm("{ .reg .u64 t; cvta.to.shared.u64 t, %1; cvt.u32.u64 %0, t; }"
        : "=r"(a) : "l"(p));
    return a;
}
// D(16x8,f32) += A(16x16,f16) * B(16x8,f16)
__device__ __forceinline__ void mma16(float* d, const uint32_t* a, const uint32_t* b) {
    asm volatile(
        "mma.sync.aligned.m16n8k16.row.col.f32.f16.f16.f32 "
        "{%0,%1,%2,%3}, {%4,%5,%6,%7}, {%8,%9}, {%0,%1,%2,%3};"
        : "+f"(d[0]), "+f"(d[1]), "+f"(d[2]), "+f"(d[3])
        : "r"(a[0]), "r"(a[1]), "r"(a[2]), "r"(a[3]), "r"(b[0]), "r"(b[1]));
}
// load 4 8x8 b16 matrices; matrix i row addrs from lanes 8i..8i+7
__device__ __forceinline__ void ldsm4(uint32_t* d, uint32_t addr) {
    asm volatile("ldmatrix.sync.aligned.m8n8.x4.shared.b16 {%0,%1,%2,%3}, [%4];"
        : "=r"(d[0]), "=r"(d[1]), "=r"(d[2]), "=r"(d[3]) : "r"(addr));
}
__device__ __forceinline__ void ldsm4t(uint32_t* d, uint32_t addr) {
    asm volatile("ldmatrix.sync.aligned.m8n8.x4.trans.shared.b16 {%0,%1,%2,%3}, [%4];"
        : "=r"(d[0]), "=r"(d[1]), "=r"(d[2]), "=r"(d[3]) : "r"(addr));
}

// ===========================================================================
// Kernel 1: QKV projection (R10 version, unchanged control).
// ===========================================================================
#define QW 36   // 32 data u32 (64 halves) + 4 pad: ldmatrix conflict-free

__global__ __launch_bounds__(256, 2) void qkv_mma_kernel(
    const float* __restrict__ hidden,
    const float* __restrict__ Wq, const float* __restrict__ bq,
    const float* __restrict__ Wk, const float* __restrict__ bk,
    const float* __restrict__ Wv, const float* __restrict__ bv,
    float* __restrict__ kout, float* __restrict__ vout)
{
    __shared__ uint32_t sA[128 * QW];
    __shared__ uint32_t sB[128 * QW];

    const int tid = threadIdx.x, lane = tid & 31, warp = tid >> 5;
    const int gid = lane >> 2, tig = lane & 3;
    const int nt = blockIdx.x, mt = blockIdx.y, sel = blockIdx.z;

    const float* W    = (sel == 0) ? Wq : (sel == 1) ? Wk : Wv;
    const float* bias = (sel == 0) ? bq : (sel == 1) ? bk : bv;
    float* dst        = (sel == 0) ? g_q : (sel == 1) ? kout : vout;

    const int m0 = mt * 128, n0 = nt * 128;
    const int wm = (warp >> 2) * 64, wn = (warp & 3) * 32;

    const uint32_t sAu = smem_u32(sA), sBu = smem_u32(sB);
    const int arow = ((lane >> 3) & 1) * 8 + (lane & 7);
    const int acol = (lane >> 4) * 4;
    const int brow = (lane >> 4) * 8 + (lane & 7);
    const int bcol = ((lane >> 3) & 1) * 4;

    float acc[4][4][4];
#pragma unroll
    for (int mi = 0; mi < 4; mi++)
#pragma unroll
        for (int ni = 0; ni < 4; ni++)
#pragma unroll
            for (int j = 0; j < 4; j++) acc[mi][ni][j] = 0.f;

    for (int i = 0; i < 12; i++) {
        const int k0 = i * 64;
        __syncthreads();
        {
            float4 va[8];
#pragma unroll
            for (int p = 0; p < 4; p++) {
                int g = p * 256 + tid;
                const float* src = hidden + (size_t)(m0 + (g >> 3)) * H_ + k0 + (g & 7) * 8;
                va[2*p]   = *(const float4*)(src);
                va[2*p+1] = *(const float4*)(src + 4);
            }
#pragma unroll
            for (int p = 0; p < 4; p++) {
                int g = p * 256 + tid;
                uint4 t;
                t.x = packh2(va[2*p].x,   va[2*p].y);
                t.y = packh2(va[2*p].z,   va[2*p].w);
                t.z = packh2(va[2*p+1].x, va[2*p+1].y);
                t.w = packh2(va[2*p+1].z, va[2*p+1].w);
                *(uint4*)&sA[(g >> 3) * QW + (g & 7) * 4] = t;
            }
#pragma unroll
            for (int p = 0; p < 4; p++) {
                int g = p * 256 + tid;
                const float* src = W + (size_t)(n0 + (g >> 3)) * H_ + k0 + (g & 7) * 8;
                va[2*p]   = *(const float4*)(src);
                va[2*p+1] = *(const float4*)(src + 4);
            }
#pragma unroll
            for (int p = 0; p < 4; p++) {
                int g = p * 256 + tid;
                uint4 t;
                t.x = packh2(va[2*p].x,   va[2*p].y);
                t.y = packh2(va[2*p].z,   va[2*p].w);
                t.z = packh2(va[2*p+1].x, va[2*p+1].y);
                t.w = packh2(va[2*p+1].z, va[2*p+1].w);
                *(uint4*)&sB[(g >> 3) * QW + (g & 7) * 4] = t;
            }
        }
        __syncthreads();

#pragma unroll
        for (int kg = 0; kg < 4; kg++) {
            uint32_t a[4][4], bf[4][2];
#pragma unroll
            for (int mi = 0; mi < 4; mi++) {
                uint32_t addr = sAu + (uint32_t)(((wm + mi * 16 + arow) * QW
                                                  + kg * 8 + acol) * 4);
                ldsm4(a[mi], addr);
            }
#pragma unroll
            for (int j = 0; j < 2; j++) {
                uint32_t d[4];
                uint32_t addr = sBu + (uint32_t)(((wn + j * 16 + brow) * QW
                                                  + kg * 8 + bcol) * 4);
                ldsm4(d, addr);
                bf[2*j][0]   = d[0]; bf[2*j][1]   = d[1];
                bf[2*j+1][0] = d[2]; bf[2*j+1][1] = d[3];
            }
#pragma unroll
            for (int mi = 0; mi < 4; mi++)
#pragma unroll
                for (int ni = 0; ni < 4; ni++)
                    mma16(acc[mi][ni], a[mi], bf[ni]);
        }
    }

#pragma unroll
    for (int ni = 0; ni < 4; ni++) {
        int gn = n0 + wn + ni * 8 + 2 * tig;
        float b0 = __ldg(bias + gn), b1 = __ldg(bias + gn + 1);
        int hh = gn >> 6, dd = gn & 63;
#pragma unroll
        for (int mi = 0; mi < 4; mi++) {
            int gm = m0 + wm + mi * 16 + gid;
            int bb = gm >> 6, ss = gm & 63;
            float2 v0 = { acc[mi][ni][0] + b0, acc[mi][ni][1] + b1 };
            *(float2*)(dst + (((size_t)bb * NH_ + hh) * S_ + ss) * HD_ + dd) = v0;
            int gm2 = gm + 8;
            bb = gm2 >> 6; ss = gm2 & 63;
            float2 v1 = { acc[mi][ni][2] + b0, acc[mi][ni][3] + b1 };
            *(float2*)(dst + (((size_t)bb * NH_ + hh) * S_ + ss) * HD_ + dd) = v1;
        }
    }
}

// ===========================================================================
// Kernel 2: attention, fp16 m16n8k16 + online softmax.
// R11: V staged coalesced [key][dim] (like K); K frags via ldmatrix,
// V frags via ldmatrix.trans. Structure otherwise R8-identical.
// ===========================================================================
#define KW 36   // 32 data u32 + 4 pad (qs, ks, vs rows)

__global__ __launch_bounds__(128) void attn_mma_kernel(
    const float* __restrict__ kout, const float* __restrict__ vout,
    const float* __restrict__ c0k,  const float* __restrict__ c0v,
    const float* __restrict__ c1k,  const float* __restrict__ c1v,
    const float* __restrict__ mask, float* __restrict__ out)
{
    __shared__ uint32_t qs[64 * KW];     // Q: 64 rows x 64 halves
    __shared__ uint32_t ks[32 * KW];     // K: 32 keys x 64 halves
    __shared__ uint32_t vs[32 * KW];     // V: 32 keys x 64 halves
    __shared__ float msm[32];

    const unsigned FULL = 0xffffffffu;
    const int bh = blockIdx.x, b = bh / NH_, h = bh % NH_;
    const int tid = threadIdx.x, lane = tid & 31, warp = tid >> 5;
    const int gid = lane >> 2, tig = lane & 3;

    const uint32_t ksu = smem_u32(ks), vsu = smem_u32(vs);
    // K (non-trans) ldsm4 lane coords: covers (2 nb x 2 k-halves)
    const int krow = (lane >> 4) * 8 + (lane & 7);        // nb-within-pair
    const int kcol = ((lane >> 3) & 1) * 4;               // k-half
    // V (trans) ldsm4 lane coords: covers (2 key-halves x 2 nd blocks)
    const int vrow = ((lane >> 3) & 1) * 8 + (lane & 7);  // key-half
    const int vcol = (lane >> 4) * 4;                     // nd-within-pair

    // stage Q (pre-scaled by 1/8) as packed fp16
    {
        const float* qp = g_q + (size_t)bh * S_ * HD_;
#pragma unroll
        for (int p = 0; p < 8; p++) {
            int idx = p * 128 + tid;
            int r = idx >> 4, c4 = idx & 15;
            float4 v = *(const float4*)(qp + r * HD_ + c4 * 4);
            uint2 t = { packh2(v.x * 0.125f, v.y * 0.125f),
                        packh2(v.z * 0.125f, v.w * 0.125f) };
            *(uint2*)&qs[r * KW + c4 * 2] = t;
        }
    }
    __syncthreads();

    // Q fragments: qf[kk] covers k-dims 16*kk .. 16*kk+15
    uint32_t qf[4][4];
    {
        const int r = warp * 16 + gid;
#pragma unroll
        for (int kk = 0; kk < 4; kk++) {
            int c = kk * 8 + tig;
            qf[kk][0] = qs[r * KW + c];
            qf[kk][1] = qs[(r + 8) * KW + c];
            qf[kk][2] = qs[r * KW + c + 4];
            qf[kk][3] = qs[(r + 8) * KW + c + 4];
        }
    }

    float o[8][4];
#pragma unroll
    for (int nd = 0; nd < 8; nd++)
#pragma unroll
        for (int j = 0; j < 4; j++) o[nd][j] = 0.f;
    float m0 = -1e30f, m1 = -1e30f, l0 = 0.f, l1 = 0.f;

    const float* maskb = mask + (size_t)b * LT_;

    for (int seg = 0; seg < 3; seg++) {
        const float *kb, *vb;
        int len, posbase;
        if (seg == 0) {
            size_t off = ((size_t)(b % BS_) * NH_ + h) * L0_ * HD_;
            kb = c0k + off; vb = c0v + off; len = L0_; posbase = 0;
        } else if (seg == 1) {
            size_t off = ((size_t)b * NH_ + h) * L1_ * HD_;
            kb = c1k + off; vb = c1v + off; len = L1_; posbase = L0_;
        } else {
            size_t off = ((size_t)b * NH_ + h) * S_ * HD_;
            kb = kout + off; vb = vout + off; len = S_; posbase = L0_ + L1_;
        }

        for (int t = 0; t < len; t += 32) {
            __syncthreads();
            // K and V: rows = keys, packed along d (both coalesced)
#pragma unroll
            for (int p = 0; p < 4; p++) {
                int idx = p * 128 + tid;
                int r = idx >> 4, c4 = idx & 15;
                float4 kv = *(const float4*)(kb + (size_t)(t + r) * HD_ + c4 * 4);
                uint2 tk = { packh2(kv.x, kv.y), packh2(kv.z, kv.w) };
                *(uint2*)&ks[r * KW + c4 * 2] = tk;
            }
#pragma unroll
            for (int p = 0; p < 4; p++) {
                int idx = p * 128 + tid;
                int r = idx >> 4, c4 = idx & 15;
                float4 vv = *(const float4*)(vb + (size_t)(t + r) * HD_ + c4 * 4);
                uint2 tv = { packh2(vv.x, vv.y), packh2(vv.z, vv.w) };
                *(uint2*)&vs[r * KW + c4 * 2] = tv;
            }
            if (tid < 32) msm[tid] = maskb[posbase + t + tid];
            __syncthreads();

            // scores: S[16 rows][32 keys] per warp; K frags via ldsm4
            float sc[4][4];
#pragma unroll
            for (int nb = 0; nb < 4; nb++)
                sc[nb][0] = sc[nb][1] = sc[nb][2] = sc[nb][3] = 0.f;
#pragma unroll
            for (int kk = 0; kk < 4; kk++) {
#pragma unroll
                for (int nbp = 0; nbp < 2; nbp++) {
                    uint32_t d[4];
                    uint32_t addr = ksu + (uint32_t)(((nbp * 16 + krow) * KW
                                                      + kk * 8 + kcol) * 4);
                    ldsm4(d, addr);
                    mma16(sc[2*nbp],     qf[kk], &d[0]);
                    mma16(sc[2*nbp + 1], qf[kk], &d[2]);
                }
            }
#pragma unroll
            for (int nb = 0; nb < 4; nb++) {
                float mk0 = msm[nb * 8 + 2 * tig], mk1 = msm[nb * 8 + 2 * tig + 1];
                sc[nb][0] += mk0; sc[nb][1] += mk1;
                sc[nb][2] += mk0; sc[nb][3] += mk1;
            }

            // online softmax (rows r = gid and r+8)
            float tm0 = -1e30f, tm1 = -1e30f;
#pragma unroll
            for (int nb = 0; nb < 4; nb++) {
                tm0 = fmaxf(tm0, fmaxf(sc[nb][0], sc[nb][1]));
                tm1 = fmaxf(tm1, fmaxf(sc[nb][2], sc[nb][3]));
            }
            tm0 = fmaxf(tm0, __shfl_xor_sync(FULL, tm0, 1));
            tm0 = fmaxf(tm0, __shfl_xor_sync(FULL, tm0, 2));
            tm1 = fmaxf(tm1, __shfl_xor_sync(FULL, tm1, 1));
            tm1 = fmaxf(tm1, __shfl_xor_sync(FULL, tm1, 2));
            float nm0 = fmaxf(m0, tm0), nm1 = fmaxf(m1, tm1);
            float cr0 = __expf(m0 - nm0), cr1 = __expf(m1 - nm1);
            m0 = nm0; m1 = nm1;
            l0 *= cr0; l1 *= cr1;

            // exp + pack P directly into k16 A-fragments (no shuffles)
            uint32_t pa[2][4];
#pragma unroll
            for (int kc = 0; kc < 2; kc++) {
                float p00 = __expf(sc[2*kc][0]   - m0), p01 = __expf(sc[2*kc][1]   - m0);
                float p02 = __expf(sc[2*kc][2]   - m1), p03 = __expf(sc[2*kc][3]   - m1);
                float p10 = __expf(sc[2*kc+1][0] - m0), p11 = __expf(sc[2*kc+1][1] - m0);
                float p12 = __expf(sc[2*kc+1][2] - m1), p13 = __expf(sc[2*kc+1][3] - m1);
                l0 += p00 + p01 + p10 + p11;
                l1 += p02 + p03 + p12 + p13;
                pa[kc][0] = packh2(p00, p01);
                pa[kc][1] = packh2(p02, p03);
                pa[kc][2] = packh2(p10, p11);
                pa[kc][3] = packh2(p12, p13);
            }
#pragma unroll
            for (int nd = 0; nd < 8; nd++) {
                o[nd][0] *= cr0; o[nd][1] *= cr0;
                o[nd][2] *= cr1; o[nd][3] *= cr1;
            }

            // P @ V : V frags via ldsm4.trans from [key][dim] tile
#pragma unroll
            for (int kc = 0; kc < 2; kc++) {
#pragma unroll
                for (int ndp = 0; ndp < 4; ndp++) {
                    uint32_t d[4];
                    uint32_t addr = vsu + (uint32_t)(((kc * 16 + vrow) * KW
                                                      + ndp * 8 + vcol) * 4);
                    ldsm4t(d, addr);
                    mma16(o[2*ndp],     pa[kc], &d[0]);
                    mma16(o[2*ndp + 1], pa[kc], &d[2]);
                }
            }
        }
    }

    l0 += __shfl_xor_sync(FULL, l0, 1);
    l0 += __shfl_xor_sync(FULL, l0, 2);
    l1 += __shfl_xor_sync(FULL, l1, 1);
    l1 += __shfl_xor_sync(FULL, l1, 2);
    float i0 = 1.f / l0, i1 = 1.f / l1;

    const int s = warp * 16 + gid;
    float* ob  = out + ((size_t)b * S_ + s) * H_ + h * HD_;
    float* ob2 = out + ((size_t)b * S_ + s + 8) * H_ + h * HD_;
#pragma unroll
    for (int nd = 0; nd < 8; nd++) {
        int d = nd * 8 + 2 * tig;
        float2 v0 = { o[nd][0] * i0, o[nd][1] * i0 };
        float2 v1 = { o[nd][2] * i1, o[nd][3] * i1 };
        *(float2*)(ob + d)  = v0;
        *(float2*)(ob2 + d) = v1;
    }
}

// ---------------------------------------------------------------------------
extern "C" void kernel_launch(void* const* d_in, const int* in_sizes, int n_in,
                              void* d_out, int out_size)
{
    const float* hidden = (const float*)d_in[0];
    const float* mask   = (const float*)d_in[1];
    const float* Wq     = (const float*)d_in[2];
    const float* bq     = (const float*)d_in[3];
    const float* Wk     = (const float*)d_in[4];
    const float* bk     = (const float*)d_in[5];
    const float* Wv     = (const float*)d_in[6];
    const float* bv     = (const float*)d_in[7];
    const float* c0k    = (const float*)d_in[8];
    const float* c0v    = (const float*)d_in[9];
    const float* c1k    = (const float*)d_in[10];
    const float* c1v    = (const float*)d_in[11];

    float* out  = (float*)d_out;
    float* kout = out + (size_t)OUTSZ;
    float* vout = out + (size_t)2 * OUTSZ;

    dim3 g1(6, 120, 3);
    qkv_mma_kernel<<<g1, 256>>>(hidden, Wq, bq, Wk, bk, Wv, bv, kout, vout);

    attn_mma_kernel<<<B_ * NH_, 128>>>(kout, vout, c0k, c0v, c1k, c1v, mask, out);
}

// round 12
// speedup vs baseline: 1.4029x; 1.0005x over previous
#include <cuda_runtime.h>
#include <cuda_fp16.h>
#include <cstdint>

// Problem constants (fixed shapes)
#define B_    240
#define S_    64
#define H_    768
#define NH_   12
#define HD_   64
#define L0_   384
#define L1_   128
#define LT_   576          // L0+L1+S
#define BS_   8            // cache0 batch = 240/30
#define OUTSZ (B_*S_*H_)   // 11796480

// scratch for q in [B, nh, S, hd] layout (fp32)
__device__ float g_q[B_ * NH_ * S_ * HD_];

// ---------------------------------------------------------------------------
// helpers
// ---------------------------------------------------------------------------
__device__ __forceinline__ uint32_t packh2(float lo, float hi) {
    __half2 h = __floats2half2_rn(lo, hi);     // .x = lo (low 16 bits)
    return *reinterpret_cast<uint32_t*>(&h);
}
__device__ __forceinline__ uint32_t smem_u32(const void* p) {
    uint32_t a;
    asm("{ .reg .u64 t; cvta.to.shared.u64 t, %1; cvt.u32.u64 %0, t; }"
        : "=r"(a) : "l"(p));
    return a;
}
// D(16x8,f32) += A(16x16,f16) * B(16x8,f16)
__device__ __forceinline__ void mma16(float* d, const uint32_t* a, const uint32_t* b) {
    asm volatile(
        "mma.sync.aligned.m16n8k16.row.col.f32.f16.f16.f32 "
        "{%0,%1,%2,%3}, {%4,%5,%6,%7}, {%8,%9}, {%0,%1,%2,%3};"
        : "+f"(d[0]), "+f"(d[1]), "+f"(d[2]), "+f"(d[3])
        : "r"(a[0]), "r"(a[1]), "r"(a[2]), "r"(a[3]), "r"(b[0]), "r"(b[1]));
}
// load 4 8x8 b16 matrices; matrix i row addrs from lanes 8i..8i+7
__device__ __forceinline__ void ldsm4(uint32_t* d, uint32_t addr) {
    asm volatile("ldmatrix.sync.aligned.m8n8.x4.shared.b16 {%0,%1,%2,%3}, [%4];"
        : "=r"(d[0]), "=r"(d[1]), "=r"(d[2]), "=r"(d[3]) : "r"(addr));
}
__device__ __forceinline__ void ldsm4t(uint32_t* d, uint32_t addr) {
    asm volatile("ldmatrix.sync.aligned.m8n8.x4.trans.shared.b16 {%0,%1,%2,%3}, [%4];"
        : "=r"(d[0]), "=r"(d[1]), "=r"(d[2]), "=r"(d[3]) : "r"(addr));
}

// ===========================================================================
// Kernel 1: QKV projection via fp16 m16n8k16 + ldmatrix.
// R12: BK=32, double-buffered smem, register-prefetch pipeline:
//   LDG(i+1) raw -> compute(i) -> cvt+STS(i+1) -> one sync.
// 128x128 CTA tile, 256 thr (8 warps, 64x32 warp tile), 24 chunks.
// ===========================================================================
#define QW 20                 // 16 data u32 (32 halves) + 4 pad
#define QBUF (128 * QW)       // u32 per matrix per buffer

__global__ __launch_bounds__(256, 2) void qkv_mma_kernel(
    const float* __restrict__ hidden,
    const float* __restrict__ Wq, const float* __restrict__ bq,
    const float* __restrict__ Wk, const float* __restrict__ bk,
    const float* __restrict__ Wv, const float* __restrict__ bv,
    float* __restrict__ kout, float* __restrict__ vout)
{
    __shared__ uint32_t sA[2][QBUF];
    __shared__ uint32_t sB[2][QBUF];   // 40 KB total

    const int tid = threadIdx.x, lane = tid & 31, warp = tid >> 5;
    const int gid = lane >> 2, tig = lane & 3;
    const int nt = blockIdx.x, mt = blockIdx.y, sel = blockIdx.z;

    const float* W    = (sel == 0) ? Wq : (sel == 1) ? Wk : Wv;
    const float* bias = (sel == 0) ? bq : (sel == 1) ? bk : bv;
    float* dst        = (sel == 0) ? g_q : (sel == 1) ? kout : vout;

    const int m0 = mt * 128, n0 = nt * 128;
    const int wm = (warp >> 2) * 64, wn = (warp & 3) * 32;

    // ldmatrix lane coords (as validated in R10)
    const uint32_t sAu = smem_u32(sA), sBu = smem_u32(sB);
    const int arow = ((lane >> 3) & 1) * 8 + (lane & 7);
    const int acol = (lane >> 4) * 4;
    const int brow = (lane >> 4) * 8 + (lane & 7);
    const int bcol = ((lane >> 3) & 1) * 4;

    // staging coords: 8 threads per row (32 floats), 4 passes of 32 rows
    const int srow = tid >> 3;          // 0..31
    const int scol = (tid & 7) * 4;     // float offset 0..28
    const int su   = (tid & 7) * 2;     // u32 offset in smem row

    float acc[4][4][4];
#pragma unroll
    for (int mi = 0; mi < 4; mi++)
#pragma unroll
        for (int ni = 0; ni < 4; ni++)
#pragma unroll
            for (int j = 0; j < 4; j++) acc[mi][ni][j] = 0.f;

    float4 ra[4], rb[4];

    // prologue: chunk 0 into buf 0
#pragma unroll
    for (int p = 0; p < 4; p++) {
        ra[p] = *(const float4*)(hidden + (size_t)(m0 + p * 32 + srow) * H_ + scol);
        rb[p] = *(const float4*)(W      + (size_t)(n0 + p * 32 + srow) * H_ + scol);
    }
#pragma unroll
    for (int p = 0; p < 4; p++) {
        *(uint2*)&sA[0][(p * 32 + srow) * QW + su] =
            make_uint2(packh2(ra[p].x, ra[p].y), packh2(ra[p].z, ra[p].w));
        *(uint2*)&sB[0][(p * 32 + srow) * QW + su] =
            make_uint2(packh2(rb[p].x, rb[p].y), packh2(rb[p].z, rb[p].w));
    }
    __syncthreads();

#pragma unroll 2
    for (int i = 0; i < 24; i++) {
        const int buf = i & 1;
        // prefetch chunk i+1 (raw fp32, held in regs through compute)
        if (i + 1 < 24) {
            const int k0 = (i + 1) * 32;
#pragma unroll
            for (int p = 0; p < 4; p++) {
                ra[p] = *(const float4*)(hidden + (size_t)(m0 + p * 32 + srow) * H_ + k0 + scol);
                rb[p] = *(const float4*)(W      + (size_t)(n0 + p * 32 + srow) * H_ + k0 + scol);
            }
        }

        // compute chunk i from buf
        const uint32_t sAb = sAu + (uint32_t)(buf * QBUF * 4);
        const uint32_t sBb = sBu + (uint32_t)(buf * QBUF * 4);
#pragma unroll
        for (int kg = 0; kg < 2; kg++) {
            uint32_t a[4][4], bf[4][2];
#pragma unroll
            for (int mi = 0; mi < 4; mi++) {
                uint32_t addr = sAb + (uint32_t)(((wm + mi * 16 + arow) * QW
                                                  + kg * 8 + acol) * 4);
                ldsm4(a[mi], addr);
            }
#pragma unroll
            for (int j = 0; j < 2; j++) {
                uint32_t d[4];
                uint32_t addr = sBb + (uint32_t)(((wn + j * 16 + brow) * QW
                                                  + kg * 8 + bcol) * 4);
                ldsm4(d, addr);
                bf[2*j][0]   = d[0]; bf[2*j][1]   = d[1];
                bf[2*j+1][0] = d[2]; bf[2*j+1][1] = d[3];
            }
#pragma unroll
            for (int mi = 0; mi < 4; mi++)
#pragma unroll
                for (int ni = 0; ni < 4; ni++)
                    mma16(acc[mi][ni], a[mi], bf[ni]);
        }

        // cvt + store chunk i+1 into the other buffer
        if (i + 1 < 24) {
            const int nb = buf ^ 1;
#pragma unroll
            for (int p = 0; p < 4; p++) {
                *(uint2*)&sA[nb][(p * 32 + srow) * QW + su] =
                    make_uint2(packh2(ra[p].x, ra[p].y), packh2(ra[p].z, ra[p].w));
                *(uint2*)&sB[nb][(p * 32 + srow) * QW + su] =
                    make_uint2(packh2(rb[p].x, rb[p].y), packh2(rb[p].z, rb[p].w));
            }
        }
        __syncthreads();
    }

    // epilogue: bias + store into [B, nh, S, hd]
#pragma unroll
    for (int ni = 0; ni < 4; ni++) {
        int gn = n0 + wn + ni * 8 + 2 * tig;
        float b0 = __ldg(bias + gn), b1 = __ldg(bias + gn + 1);
        int hh = gn >> 6, dd = gn & 63;
#pragma unroll
        for (int mi = 0; mi < 4; mi++) {
            int gm = m0 + wm + mi * 16 + gid;
            int bb = gm >> 6, ss = gm & 63;
            float2 v0 = { acc[mi][ni][0] + b0, acc[mi][ni][1] + b1 };
            *(float2*)(dst + (((size_t)bb * NH_ + hh) * S_ + ss) * HD_ + dd) = v0;
            int gm2 = gm + 8;
            bb = gm2 >> 6; ss = gm2 & 63;
            float2 v1 = { acc[mi][ni][2] + b0, acc[mi][ni][3] + b1 };
            *(float2*)(dst + (((size_t)bb * NH_ + hh) * S_ + ss) * HD_ + dd) = v1;
        }
    }
}

// ===========================================================================
// Kernel 2: attention (R11 version verbatim — the 159.5us control)
// ===========================================================================
#define KW 36   // 32 data u32 + 4 pad (qs, ks, vs rows)

__global__ __launch_bounds__(128) void attn_mma_kernel(
    const float* __restrict__ kout, const float* __restrict__ vout,
    const float* __restrict__ c0k,  const float* __restrict__ c0v,
    const float* __restrict__ c1k,  const float* __restrict__ c1v,
    const float* __restrict__ mask, float* __restrict__ out)
{
    __shared__ uint32_t qs[64 * KW];     // Q: 64 rows x 64 halves
    __shared__ uint32_t ks[32 * KW];     // K: 32 keys x 64 halves
    __shared__ uint32_t vs[32 * KW];     // V: 32 keys x 64 halves
    __shared__ float msm[32];

    const unsigned FULL = 0xffffffffu;
    const int bh = blockIdx.x, b = bh / NH_, h = bh % NH_;
    const int tid = threadIdx.x, lane = tid & 31, warp = tid >> 5;
    const int gid = lane >> 2, tig = lane & 3;

    const uint32_t ksu = smem_u32(ks), vsu = smem_u32(vs);
    const int krow = (lane >> 4) * 8 + (lane & 7);        // K: nb-within-pair
    const int kcol = ((lane >> 3) & 1) * 4;               // K: k-half
    const int vrow = ((lane >> 3) & 1) * 8 + (lane & 7);  // V: key-half
    const int vcol = (lane >> 4) * 4;                     // V: nd-within-pair

    // stage Q (pre-scaled by 1/8) as packed fp16
    {
        const float* qp = g_q + (size_t)bh * S_ * HD_;
#pragma unroll
        for (int p = 0; p < 8; p++) {
            int idx = p * 128 + tid;
            int r = idx >> 4, c4 = idx & 15;
            float4 v = *(const float4*)(qp + r * HD_ + c4 * 4);
            uint2 t = { packh2(v.x * 0.125f, v.y * 0.125f),
                        packh2(v.z * 0.125f, v.w * 0.125f) };
            *(uint2*)&qs[r * KW + c4 * 2] = t;
        }
    }
    __syncthreads();

    uint32_t qf[4][4];
    {
        const int r = warp * 16 + gid;
#pragma unroll
        for (int kk = 0; kk < 4; kk++) {
            int c = kk * 8 + tig;
            qf[kk][0] = qs[r * KW + c];
            qf[kk][1] = qs[(r + 8) * KW + c];
            qf[kk][2] = qs[r * KW + c + 4];
            qf[kk][3] = qs[(r + 8) * KW + c + 4];
        }
    }

    float o[8][4];
#pragma unroll
    for (int nd = 0; nd < 8; nd++)
#pragma unroll
        for (int j = 0; j < 4; j++) o[nd][j] = 0.f;
    float m0 = -1e30f, m1 = -1e30f, l0 = 0.f, l1 = 0.f;

    const float* maskb = mask + (size_t)b * LT_;

    for (int seg = 0; seg < 3; seg++) {
        const float *kb, *vb;
        int len, posbase;
        if (seg == 0) {
            size_t off = ((size_t)(b % BS_) * NH_ + h) * L0_ * HD_;
            kb = c0k + off; vb = c0v + off; len = L0_; posbase = 0;
        } else if (seg == 1) {
            size_t off = ((size_t)b * NH_ + h) * L1_ * HD_;
            kb = c1k + off; vb = c1v + off; len = L1_; posbase = L0_;
        } else {
            size_t off = ((size_t)b * NH_ + h) * S_ * HD_;
            kb = kout + off; vb = vout + off; len = S_; posbase = L0_ + L1_;
        }

        for (int t = 0; t < len; t += 32) {
            __syncthreads();
#pragma unroll
            for (int p = 0; p < 4; p++) {
                int idx = p * 128 + tid;
                int r = idx >> 4, c4 = idx & 15;
                float4 kv = *(const float4*)(kb + (size_t)(t + r) * HD_ + c4 * 4);
                uint2 tk = { packh2(kv.x, kv.y), packh2(kv.z, kv.w) };
                *(uint2*)&ks[r * KW + c4 * 2] = tk;
            }
#pragma unroll
            for (int p = 0; p < 4; p++) {
                int idx = p * 128 + tid;
                int r = idx >> 4, c4 = idx & 15;
                float4 vv = *(const float4*)(vb + (size_t)(t + r) * HD_ + c4 * 4);
                uint2 tv = { packh2(vv.x, vv.y), packh2(vv.z, vv.w) };
                *(uint2*)&vs[r * KW + c4 * 2] = tv;
            }
            if (tid < 32) msm[tid] = maskb[posbase + t + tid];
            __syncthreads();

            float sc[4][4];
#pragma unroll
            for (int nb = 0; nb < 4; nb++)
                sc[nb][0] = sc[nb][1] = sc[nb][2] = sc[nb][3] = 0.f;
#pragma unroll
            for (int kk = 0; kk < 4; kk++) {
#pragma unroll
                for (int nbp = 0; nbp < 2; nbp++) {
                    uint32_t d[4];
                    uint32_t addr = ksu + (uint32_t)(((nbp * 16 + krow) * KW
                                                      + kk * 8 + kcol) * 4);
                    ldsm4(d, addr);
                    mma16(sc[2*nbp],     qf[kk], &d[0]);
                    mma16(sc[2*nbp + 1], qf[kk], &d[2]);
                }
            }
#pragma unroll
            for (int nb = 0; nb < 4; nb++) {
                float mk0 = msm[nb * 8 + 2 * tig], mk1 = msm[nb * 8 + 2 * tig + 1];
                sc[nb][0] += mk0; sc[nb][1] += mk1;
                sc[nb][2] += mk0; sc[nb][3] += mk1;
            }

            float tm0 = -1e30f, tm1 = -1e30f;
#pragma unroll
            for (int nb = 0; nb < 4; nb++) {
                tm0 = fmaxf(tm0, fmaxf(sc[nb][0], sc[nb][1]));
                tm1 = fmaxf(tm1, fmaxf(sc[nb][2], sc[nb][3]));
            }
            tm0 = fmaxf(tm0, __shfl_xor_sync(FULL, tm0, 1));
            tm0 = fmaxf(tm0, __shfl_xor_sync(FULL, tm0, 2));
            tm1 = fmaxf(tm1, __shfl_xor_sync(FULL, tm1, 1));
            tm1 = fmaxf(tm1, __shfl_xor_sync(FULL, tm1, 2));
            float nm0 = fmaxf(m0, tm0), nm1 = fmaxf(m1, tm1);
            float cr0 = __expf(m0 - nm0), cr1 = __expf(m1 - nm1);
            m0 = nm0; m1 = nm1;
            l0 *= cr0; l1 *= cr1;

            uint32_t pa[2][4];
#pragma unroll
            for (int kc = 0; kc < 2; kc++) {
                float p00 = __expf(sc[2*kc][0]   - m0), p01 = __expf(sc[2*kc][1]   - m0);
                float p02 = __expf(sc[2*kc][2]   - m1), p03 = __expf(sc[2*kc][3]   - m1);
                float p10 = __expf(sc[2*kc+1][0] - m0), p11 = __expf(sc[2*kc+1][1] - m0);
                float p12 = __expf(sc[2*kc+1][2] - m1), p13 = __expf(sc[2*kc+1][3] - m1);
                l0 += p00 + p01 + p10 + p11;
                l1 += p02 + p03 + p12 + p13;
                pa[kc][0] = packh2(p00, p01);
                pa[kc][1] = packh2(p02, p03);
                pa[kc][2] = packh2(p10, p11);
                pa[kc][3] = packh2(p12, p13);
            }
#pragma unroll
            for (int nd = 0; nd < 8; nd++) {
                o[nd][0] *= cr0; o[nd][1] *= cr0;
                o[nd][2] *= cr1; o[nd][3] *= cr1;
            }

#pragma unroll
            for (int kc = 0; kc < 2; kc++) {
#pragma unroll
                for (int ndp = 0; ndp < 4; ndp++) {
                    uint32_t d[4];
                    uint32_t addr = vsu + (uint32_t)(((kc * 16 + vrow) * KW
                                                      + ndp * 8 + vcol) * 4);
                    ldsm4t(d, addr);
                    mma16(o[2*ndp],     pa[kc], &d[0]);
                    mma16(o[2*ndp + 1], pa[kc], &d[2]);
                }
            }
        }
    }

    l0 += __shfl_xor_sync(FULL, l0, 1);
    l0 += __shfl_xor_sync(FULL, l0, 2);
    l1 += __shfl_xor_sync(FULL, l1, 1);
    l1 += __shfl_xor_sync(FULL, l1, 2);
    float i0 = 1.f / l0, i1 = 1.f / l1;

    const int s = warp * 16 + gid;
    float* ob  = out + ((size_t)b * S_ + s) * H_ + h * HD_;
    float* ob2 = out + ((size_t)b * S_ + s + 8) * H_ + h * HD_;
#pragma unroll
    for (int nd = 0; nd < 8; nd++) {
        int d = nd * 8 + 2 * tig;
        float2 v0 = { o[nd][0] * i0, o[nd][1] * i0 };
        float2 v1 = { o[nd][2] * i1, o[nd][3] * i1 };
        *(float2*)(ob + d)  = v0;
        *(float2*)(ob2 + d) = v1;
    }
}

// ---------------------------------------------------------------------------
extern "C" void kernel_launch(void* const* d_in, const int* in_sizes, int n_in,
                              void* d_out, int out_size)
{
    const float* hidden = (const float*)d_in[0];
    const float* mask   = (const float*)d_in[1];
    const float* Wq     = (const float*)d_in[2];
    const float* bq     = (const float*)d_in[3];
    const float* Wk     = (const float*)d_in[4];
    const float* bk     = (const float*)d_in[5];
    const float* Wv     = (const float*)d_in[6];
    const float* bv     = (const float*)d_in[7];
    const float* c0k    = (const float*)d_in[8];
    const float* c0v    = (const float*)d_in[9];
    const float* c1k    = (const float*)d_in[10];
    const float* c1v    = (const float*)d_in[11];

    float* out  = (float*)d_out;
    float* kout = out + (size_t)OUTSZ;
    float* vout = out + (size_t)2 * OUTSZ;

    dim3 g1(6, 120, 3);
    qkv_mma_kernel<<<g1, 256>>>(hidden, Wq, bq, Wk, bk, Wv, bv, kout, vout);

    attn_mma_kernel<<<B_ * NH_, 128>>>(kout, vout, c0k, c0v, c1k, c1v, mask, out);
}

// round 13
// speedup vs baseline: 1.6130x; 1.1498x over previous
#include <cuda_runtime.h>
#include <cuda_fp16.h>
#include <cstdint>

// Problem constants (fixed shapes)
#define B_    240
#define S_    64
#define H_    768
#define NH_   12
#define HD_   64
#define L0_   384
#define L1_   128
#define LT_   576          // L0+L1+S
#define BS_   8            // cache0 batch = 240/30
#define OUTSZ (B_*S_*H_)   // 11796480

// fp16-packed scratch (u32 = half2 pair along the inner dim)
__device__ uint32_t g_hidh[15360 * 384];            // hidden
__device__ uint32_t g_wh[3 * 768 * 384];            // Wq|Wk|Wv
__device__ uint32_t g_c0kh[BS_ * NH_ * L0_ * 32];   // cache0 K
__device__ uint32_t g_c0vh[BS_ * NH_ * L0_ * 32];   // cache0 V
__device__ uint32_t g_qh[B_ * NH_ * S_ * 32];       // q (pre-scaled by 1/8)
__device__ uint32_t g_kh[B_ * NH_ * S_ * 32];       // k fp16 copy
__device__ uint32_t g_vh[B_ * NH_ * S_ * 32];       // v fp16 copy

// ---------------------------------------------------------------------------
// helpers
// ---------------------------------------------------------------------------
__device__ __forceinline__ uint32_t packh2(float lo, float hi) {
    __half2 h = __floats2half2_rn(lo, hi);
    return *reinterpret_cast<uint32_t*>(&h);
}
__device__ __forceinline__ uint32_t smem_u32(const void* p) {
    uint32_t a;
    asm("{ .reg .u64 t; cvta.to.shared.u64 t, %1; cvt.u32.u64 %0, t; }"
        : "=r"(a) : "l"(p));
    return a;
}
__device__ __forceinline__ void mma16(float* d, const uint32_t* a, const uint32_t* b) {
    asm volatile(
        "mma.sync.aligned.m16n8k16.row.col.f32.f16.f16.f32 "
        "{%0,%1,%2,%3}, {%4,%5,%6,%7}, {%8,%9}, {%0,%1,%2,%3};"
        : "+f"(d[0]), "+f"(d[1]), "+f"(d[2]), "+f"(d[3])
        : "r"(a[0]), "r"(a[1]), "r"(a[2]), "r"(a[3]), "r"(b[0]), "r"(b[1]));
}
__device__ __forceinline__ void ldsm4(uint32_t* d, uint32_t addr) {
    asm volatile("ldmatrix.sync.aligned.m8n8.x4.shared.b16 {%0,%1,%2,%3}, [%4];"
        : "=r"(d[0]), "=r"(d[1]), "=r"(d[2]), "=r"(d[3]) : "r"(addr));
}
__device__ __forceinline__ void ldsm4t(uint32_t* d, uint32_t addr) {
    asm volatile("ldmatrix.sync.aligned.m8n8.x4.trans.shared.b16 {%0,%1,%2,%3}, [%4];"
        : "=r"(d[0]), "=r"(d[1]), "=r"(d[2]), "=r"(d[3]) : "r"(addr));
}

// ===========================================================================
// Kernel 0: prepack fp32 -> packed fp16 (hidden, W, c0k, c0v)
// ===========================================================================
#define NF4_HID 2949120
#define NF4_W   442368
#define NF4_C0  589824
#define NF4_TOT (NF4_HID + NF4_W + 2 * NF4_C0)

__global__ __launch_bounds__(256) void prepack_kernel(
    const float* __restrict__ hidden,
    const float* __restrict__ Wq, const float* __restrict__ Wk,
    const float* __restrict__ Wv,
    const float* __restrict__ c0k, const float* __restrict__ c0v)
{
    int f4 = blockIdx.x * 256 + threadIdx.x;
    if (f4 >= NF4_TOT) return;
    const float* src;
    uint32_t* dst;
    int off;
    if (f4 < NF4_HID) {
        src = hidden; dst = g_hidh; off = f4;
    } else if (f4 < NF4_HID + NF4_W) {
        int w = f4 - NF4_HID;
        int sel = w / (NF4_W / 3);
        off = w - sel * (NF4_W / 3);
        src = (sel == 0) ? Wq : (sel == 1) ? Wk : Wv;
        dst = g_wh + (size_t)sel * (768 * 384);
    } else if (f4 < NF4_HID + NF4_W + NF4_C0) {
        off = f4 - NF4_HID - NF4_W; src = c0k; dst = g_c0kh;
    } else {
        off = f4 - NF4_HID - NF4_W - NF4_C0; src = c0v; dst = g_c0vh;
    }
    float4 v = ((const float4*)src)[off];
    ((uint2*)dst)[off] = make_uint2(packh2(v.x, v.y), packh2(v.z, v.w));
}

// ===========================================================================
// Kernel 1: QKV projection via fp16 m16n8k16 + ldmatrix, fp16 operands.
// 128x128 CTA tile, BK=64 (4 k16 groups), 256 thr (8 warps, 64x32).
// Staging = pure uint4 copy (no cvt). Epilogue writes fp32 k/v outputs
// plus fp16 scratch copies (q only fp16, pre-scaled by 1/8).
// ===========================================================================
#define QW 36   // 32 data u32 (64 halves) + 4 pad: ldmatrix conflict-free

__global__ __launch_bounds__(256, 2) void qkv_mma_kernel(
    const float* __restrict__ bq, const float* __restrict__ bk,
    const float* __restrict__ bv,
    float* __restrict__ kout, float* __restrict__ vout)
{
    __shared__ uint32_t sA[128 * QW];
    __shared__ uint32_t sB[128 * QW];

    const int tid = threadIdx.x, lane = tid & 31, warp = tid >> 5;
    const int gid = lane >> 2, tig = lane & 3;
    const int nt = blockIdx.x, mt = blockIdx.y, sel = blockIdx.z;

    const uint32_t* Wsrc = g_wh + (size_t)sel * (768 * 384);
    const float* bias = (sel == 0) ? bq : (sel == 1) ? bk : bv;
    float* dst        = (sel == 1) ? kout : vout;
    uint32_t* hdst    = (sel == 0) ? g_qh : (sel == 1) ? g_kh : g_vh;

    const int m0 = mt * 128, n0 = nt * 128;
    const int wm = (warp >> 2) * 64, wn = (warp & 3) * 32;

    const uint32_t sAu = smem_u32(sA), sBu = smem_u32(sB);
    const int arow = ((lane >> 3) & 1) * 8 + (lane & 7);
    const int acol = (lane >> 4) * 4;
    const int brow = (lane >> 4) * 8 + (lane & 7);
    const int bcol = ((lane >> 3) & 1) * 4;

    float acc[4][4][4];
#pragma unroll
    for (int mi = 0; mi < 4; mi++)
#pragma unroll
        for (int ni = 0; ni < 4; ni++)
#pragma unroll
            for (int j = 0; j < 4; j++) acc[mi][ni][j] = 0.f;

    for (int i = 0; i < 12; i++) {
        const int k0u = i * 32;    // u32 offset within the 384-u32 row
        __syncthreads();
        {
            uint4 ta[4], tb[4];
#pragma unroll
            for (int p = 0; p < 4; p++) {
                int idx = p * 256 + tid;
                int row = idx >> 3, c4 = idx & 7;
                ta[p] = *(const uint4*)(g_hidh + (size_t)(m0 + row) * 384 + k0u + c4 * 4);
                tb[p] = *(const uint4*)(Wsrc   + (size_t)(n0 + row) * 384 + k0u + c4 * 4);
            }
#pragma unroll
            for (int p = 0; p < 4; p++) {
                int idx = p * 256 + tid;
                int row = idx >> 3, c4 = idx & 7;
                *(uint4*)&sA[row * QW + c4 * 4] = ta[p];
                *(uint4*)&sB[row * QW + c4 * 4] = tb[p];
            }
        }
        __syncthreads();

#pragma unroll
        for (int kg = 0; kg < 4; kg++) {
            uint32_t a[4][4], bf[4][2];
#pragma unroll
            for (int mi = 0; mi < 4; mi++) {
                uint32_t addr = sAu + (uint32_t)(((wm + mi * 16 + arow) * QW
                                                  + kg * 8 + acol) * 4);
                ldsm4(a[mi], addr);
            }
#pragma unroll
            for (int j = 0; j < 2; j++) {
                uint32_t d[4];
                uint32_t addr = sBu + (uint32_t)(((wn + j * 16 + brow) * QW
                                                  + kg * 8 + bcol) * 4);
                ldsm4(d, addr);
                bf[2*j][0]   = d[0]; bf[2*j][1]   = d[1];
                bf[2*j+1][0] = d[2]; bf[2*j+1][1] = d[3];
            }
#pragma unroll
            for (int mi = 0; mi < 4; mi++)
#pragma unroll
                for (int ni = 0; ni < 4; ni++)
                    mma16(acc[mi][ni], a[mi], bf[ni]);
        }
    }

    // epilogue
#pragma unroll
    for (int ni = 0; ni < 4; ni++) {
        int gn = n0 + wn + ni * 8 + 2 * tig;
        float b0 = __ldg(bias + gn), b1 = __ldg(bias + gn + 1);
        int hh = gn >> 6, dd = gn & 63;
#pragma unroll
        for (int mi = 0; mi < 4; mi++) {
#pragma unroll
            for (int rr = 0; rr < 2; rr++) {
                int gm = m0 + wm + mi * 16 + gid + rr * 8;
                float x0 = acc[mi][ni][2*rr]   + b0;
                float x1 = acc[mi][ni][2*rr+1] + b1;
                int bb = gm >> 6, ss = gm & 63;
                size_t base = ((size_t)bb * NH_ + hh) * S_ + ss;
                if (sel == 0) {
                    hdst[base * 32 + (dd >> 1)] = packh2(x0 * 0.125f, x1 * 0.125f);
                } else {
                    *(float2*)(dst + base * 64 + dd) = make_float2(x0, x1);
                    hdst[base * 32 + (dd >> 1)] = packh2(x0, x1);
                }
            }
        }
    }
}

// ===========================================================================
// Kernel 2: attention, fp16 m16n8k16 + ldmatrix(.trans) + online softmax.
// R13: Q / seg0 / seg2 stage by direct uint4 copy from fp16 scratch;
// only seg1 (c1) converts fp32 at staging.
// ===========================================================================
#define KW 36   // 32 data u32 + 4 pad (qs, ks, vs rows)

__global__ __launch_bounds__(128) void attn_mma_kernel(
    const float* __restrict__ c1k,  const float* __restrict__ c1v,
    const float* __restrict__ mask, float* __restrict__ out)
{
    __shared__ uint32_t qs[64 * KW];
    __shared__ uint32_t ks[32 * KW];
    __shared__ uint32_t vs[32 * KW];
    __shared__ float msm[32];

    const unsigned FULL = 0xffffffffu;
    const int bh = blockIdx.x, b = bh / NH_, h = bh % NH_;
    const int tid = threadIdx.x, lane = tid & 31, warp = tid >> 5;
    const int gid = lane >> 2, tig = lane & 3;

    const uint32_t ksu = smem_u32(ks), vsu = smem_u32(vs);
    const int krow = (lane >> 4) * 8 + (lane & 7);
    const int kcol = ((lane >> 3) & 1) * 4;
    const int vrow = ((lane >> 3) & 1) * 8 + (lane & 7);
    const int vcol = (lane >> 4) * 4;

    // stage Q: direct copy from fp16 scratch (already scaled by 1/8)
    {
        const uint4* qsrc = (const uint4*)(g_qh + (size_t)bh * 2048);
#pragma unroll
        for (int p = 0; p < 4; p++) {
            int idx = p * 128 + tid;
            int row = idx >> 3, c4 = idx & 7;
            *(uint4*)&qs[row * KW + c4 * 4] = qsrc[idx];
        }
    }
    __syncthreads();

    uint32_t qf[4][4];
    {
        const int r = warp * 16 + gid;
#pragma unroll
        for (int kk = 0; kk < 4; kk++) {
            int c = kk * 8 + tig;
            qf[kk][0] = qs[r * KW + c];
            qf[kk][1] = qs[(r + 8) * KW + c];
            qf[kk][2] = qs[r * KW + c + 4];
            qf[kk][3] = qs[(r + 8) * KW + c + 4];
        }
    }

    float o[8][4];
#pragma unroll
    for (int nd = 0; nd < 8; nd++)
#pragma unroll
        for (int j = 0; j < 4; j++) o[nd][j] = 0.f;
    float m0 = -1e30f, m1 = -1e30f, l0 = 0.f, l1 = 0.f;

    const float* maskb = mask + (size_t)b * LT_;

    for (int seg = 0; seg < 3; seg++) {
        const uint32_t *khs = nullptr, *vhs = nullptr;   // fp16 sources
        const float *kb = nullptr, *vb = nullptr;        // fp32 sources (seg1)
        int len, posbase;
        if (seg == 0) {
            size_t off = ((size_t)(b % BS_) * NH_ + h) * L0_ * 32;
            khs = g_c0kh + off; vhs = g_c0vh + off; len = L0_; posbase = 0;
        } else if (seg == 1) {
            size_t off = ((size_t)b * NH_ + h) * L1_ * HD_;
            kb = c1k + off; vb = c1v + off; len = L1_; posbase = L0_;
        } else {
            size_t off = ((size_t)b * NH_ + h) * S_ * 32;
            khs = g_kh + off; vhs = g_vh + off; len = S_; posbase = L0_ + L1_;
        }

        for (int t = 0; t < len; t += 32) {
            __syncthreads();
            if (seg != 1) {
                // fp16: pure uint4 copy (32 keys x 32 u32 per matrix)
                const uint4* ksrc = (const uint4*)(khs + (size_t)t * 32);
                const uint4* vsrc = (const uint4*)(vhs + (size_t)t * 32);
#pragma unroll
                for (int p = 0; p < 2; p++) {
                    int idx = p * 128 + tid;
                    int row = idx >> 3, c4 = idx & 7;
                    *(uint4*)&ks[row * KW + c4 * 4] = ksrc[idx];
                    *(uint4*)&vs[row * KW + c4 * 4] = vsrc[idx];
                }
            } else {
                // fp32 path (c1): cvt at staging
#pragma unroll
                for (int p = 0; p < 4; p++) {
                    int idx = p * 128 + tid;
                    int r = idx >> 4, c4 = idx & 15;
                    float4 kv = *(const float4*)(kb + (size_t)(t + r) * HD_ + c4 * 4);
                    uint2 tk = { packh2(kv.x, kv.y), packh2(kv.z, kv.w) };
                    *(uint2*)&ks[r * KW + c4 * 2] = tk;
                }
#pragma unroll
                for (int p = 0; p < 4; p++) {
                    int idx = p * 128 + tid;
                    int r = idx >> 4, c4 = idx & 15;
                    float4 vv = *(const float4*)(vb + (size_t)(t + r) * HD_ + c4 * 4);
                    uint2 tv = { packh2(vv.x, vv.y), packh2(vv.z, vv.w) };
                    *(uint2*)&vs[r * KW + c4 * 2] = tv;
                }
            }
            if (tid < 32) msm[tid] = maskb[posbase + t + tid];
            __syncthreads();

            // scores
            float sc[4][4];
#pragma unroll
            for (int nb = 0; nb < 4; nb++)
                sc[nb][0] = sc[nb][1] = sc[nb][2] = sc[nb][3] = 0.f;
#pragma unroll
            for (int kk = 0; kk < 4; kk++) {
#pragma unroll
                for (int nbp = 0; nbp < 2; nbp++) {
                    uint32_t d[4];
                    uint32_t addr = ksu + (uint32_t)(((nbp * 16 + krow) * KW
                                                      + kk * 8 + kcol) * 4);
                    ldsm4(d, addr);
                    mma16(sc[2*nbp],     qf[kk], &d[0]);
                    mma16(sc[2*nbp + 1], qf[kk], &d[2]);
                }
            }
#pragma unroll
            for (int nb = 0; nb < 4; nb++) {
                float mk0 = msm[nb * 8 + 2 * tig], mk1 = msm[nb * 8 + 2 * tig + 1];
                sc[nb][0] += mk0; sc[nb][1] += mk1;
                sc[nb][2] += mk0; sc[nb][3] += mk1;
            }

            // online softmax
            float tm0 = -1e30f, tm1 = -1e30f;
#pragma unroll
            for (int nb = 0; nb < 4; nb++) {
                tm0 = fmaxf(tm0, fmaxf(sc[nb][0], sc[nb][1]));
                tm1 = fmaxf(tm1, fmaxf(sc[nb][2], sc[nb][3]));
            }
            tm0 = fmaxf(tm0, __shfl_xor_sync(FULL, tm0, 1));
            tm0 = fmaxf(tm0, __shfl_xor_sync(FULL, tm0, 2));
            tm1 = fmaxf(tm1, __shfl_xor_sync(FULL, tm1, 1));
            tm1 = fmaxf(tm1, __shfl_xor_sync(FULL, tm1, 2));
            float nm0 = fmaxf(m0, tm0), nm1 = fmaxf(m1, tm1);
            float cr0 = __expf(m0 - nm0), cr1 = __expf(m1 - nm1);
            m0 = nm0; m1 = nm1;
            l0 *= cr0; l1 *= cr1;

            uint32_t pa[2][4];
#pragma unroll
            for (int kc = 0; kc < 2; kc++) {
                float p00 = __expf(sc[2*kc][0]   - m0), p01 = __expf(sc[2*kc][1]   - m0);
                float p02 = __expf(sc[2*kc][2]   - m1), p03 = __expf(sc[2*kc][3]   - m1);
                float p10 = __expf(sc[2*kc+1][0] - m0), p11 = __expf(sc[2*kc+1][1] - m0);
                float p12 = __expf(sc[2*kc+1][2] - m1), p13 = __expf(sc[2*kc+1][3] - m1);
                l0 += p00 + p01 + p10 + p11;
                l1 += p02 + p03 + p12 + p13;
                pa[kc][0] = packh2(p00, p01);
                pa[kc][1] = packh2(p02, p03);
                pa[kc][2] = packh2(p10, p11);
                pa[kc][3] = packh2(p12, p13);
            }
#pragma unroll
            for (int nd = 0; nd < 8; nd++) {
                o[nd][0] *= cr0; o[nd][1] *= cr0;
                o[nd][2] *= cr1; o[nd][3] *= cr1;
            }

            // P @ V via ldmatrix.trans
#pragma unroll
            for (int kc = 0; kc < 2; kc++) {
#pragma unroll
                for (int ndp = 0; ndp < 4; ndp++) {
                    uint32_t d[4];
                    uint32_t addr = vsu + (uint32_t)(((kc * 16 + vrow) * KW
                                                      + ndp * 8 + vcol) * 4);
                    ldsm4t(d, addr);
                    mma16(o[2*ndp],     pa[kc], &d[0]);
                    mma16(o[2*ndp + 1], pa[kc], &d[2]);
                }
            }
        }
    }

    l0 += __shfl_xor_sync(FULL, l0, 1);
    l0 += __shfl_xor_sync(FULL, l0, 2);
    l1 += __shfl_xor_sync(FULL, l1, 1);
    l1 += __shfl_xor_sync(FULL, l1, 2);
    float i0 = 1.f / l0, i1 = 1.f / l1;

    const int s = warp * 16 + gid;
    float* ob  = out + ((size_t)b * S_ + s) * H_ + h * HD_;
    float* ob2 = out + ((size_t)b * S_ + s + 8) * H_ + h * HD_;
#pragma unroll
    for (int nd = 0; nd < 8; nd++) {
        int d = nd * 8 + 2 * tig;
        float2 v0 = { o[nd][0] * i0, o[nd][1] * i0 };
        float2 v1 = { o[nd][2] * i1, o[nd][3] * i1 };
        *(float2*)(ob + d)  = v0;
        *(float2*)(ob2 + d) = v1;
    }
}

// ---------------------------------------------------------------------------
extern "C" void kernel_launch(void* const* d_in, const int* in_sizes, int n_in,
                              void* d_out, int out_size)
{
    const float* hidden = (const float*)d_in[0];
    const float* mask   = (const float*)d_in[1];
    const float* Wq     = (const float*)d_in[2];
    const float* bq     = (const float*)d_in[3];
    const float* Wk     = (const float*)d_in[4];
    const float* bk     = (const float*)d_in[5];
    const float* Wv     = (const float*)d_in[6];
    const float* bv     = (const float*)d_in[7];
    const float* c0k    = (const float*)d_in[8];
    const float* c0v    = (const float*)d_in[9];
    const float* c1k    = (const float*)d_in[10];
    const float* c1v    = (const float*)d_in[11];

    float* out  = (float*)d_out;
    float* kout = out + (size_t)OUTSZ;
    float* vout = out + (size_t)2 * OUTSZ;

    prepack_kernel<<<(NF4_TOT + 255) / 256, 256>>>(hidden, Wq, Wk, Wv, c0k, c0v);

    dim3 g1(6, 120, 3);
    qkv_mma_kernel<<<g1, 256>>>(bq, bk, bv, kout, vout);

    attn_mma_kernel<<<B_ * NH_, 128>>>(c1k, c1v, mask, out);
}

// round 14
// speedup vs baseline: 1.7782x; 1.1025x over previous
#include <cuda_runtime.h>
#include <cuda_fp16.h>
#include <cstdint>

// Problem constants (fixed shapes)
#define B_    240
#define S_    64
#define H_    768
#define NH_   12
#define HD_   64
#define L0_   384
#define L1_   128
#define LT_   576          // L0+L1+S
#define BS_   8            // cache0 batch = 240/30
#define OUTSZ (B_*S_*H_)   // 11796480

// fp16-packed scratch (u32 = half2 pair along the inner dim)
__device__ uint32_t g_hidh[15360 * 384];            // hidden
__device__ uint32_t g_wh[3 * 768 * 384];            // Wq|Wk|Wv
__device__ uint32_t g_c0kh[BS_ * NH_ * L0_ * 32];   // cache0 K
__device__ uint32_t g_c0vh[BS_ * NH_ * L0_ * 32];   // cache0 V
__device__ uint32_t g_qh[B_ * NH_ * S_ * 32];       // q (pre-scaled by 1/8)
__device__ uint32_t g_kh[B_ * NH_ * S_ * 32];       // k fp16 copy
__device__ uint32_t g_vh[B_ * NH_ * S_ * 32];       // v fp16 copy

// ---------------------------------------------------------------------------
// helpers
// ---------------------------------------------------------------------------
__device__ __forceinline__ uint32_t packh2(float lo, float hi) {
    __half2 h = __floats2half2_rn(lo, hi);
    return *reinterpret_cast<uint32_t*>(&h);
}
__device__ __forceinline__ uint32_t smem_u32(const void* p) {
    uint32_t a;
    asm("{ .reg .u64 t; cvta.to.shared.u64 t, %1; cvt.u32.u64 %0, t; }"
        : "=r"(a) : "l"(p));
    return a;
}
__device__ __forceinline__ void mma16(float* d, const uint32_t* a, const uint32_t* b) {
    asm volatile(
        "mma.sync.aligned.m16n8k16.row.col.f32.f16.f16.f32 "
        "{%0,%1,%2,%3}, {%4,%5,%6,%7}, {%8,%9}, {%0,%1,%2,%3};"
        : "+f"(d[0]), "+f"(d[1]), "+f"(d[2]), "+f"(d[3])
        : "r"(a[0]), "r"(a[1]), "r"(a[2]), "r"(a[3]), "r"(b[0]), "r"(b[1]));
}
__device__ __forceinline__ void ldsm4(uint32_t* d, uint32_t addr) {
    asm volatile("ldmatrix.sync.aligned.m8n8.x4.shared.b16 {%0,%1,%2,%3}, [%4];"
        : "=r"(d[0]), "=r"(d[1]), "=r"(d[2]), "=r"(d[3]) : "r"(addr));
}
__device__ __forceinline__ void ldsm4t(uint32_t* d, uint32_t addr) {
    asm volatile("ldmatrix.sync.aligned.m8n8.x4.trans.shared.b16 {%0,%1,%2,%3}, [%4];"
        : "=r"(d[0]), "=r"(d[1]), "=r"(d[2]), "=r"(d[3]) : "r"(addr));
}
#define CP_ASYNC16(saddr, gaddr) \
    asm volatile("cp.async.cg.shared.global [%0], [%1], 16;" \
                 :: "r"(saddr), "l"(gaddr))
#define CP_COMMIT()  asm volatile("cp.async.commit_group;")
#define CP_WAIT0()   asm volatile("cp.async.wait_group 0;")

// ===========================================================================
// Kernel 0: prepack fp32 -> packed fp16 (hidden, W, c0k, c0v)
// ===========================================================================
#define NF4_HID 2949120
#define NF4_W   442368
#define NF4_C0  589824
#define NF4_TOT (NF4_HID + NF4_W + 2 * NF4_C0)

__global__ __launch_bounds__(256) void prepack_kernel(
    const float* __restrict__ hidden,
    const float* __restrict__ Wq, const float* __restrict__ Wk,
    const float* __restrict__ Wv,
    const float* __restrict__ c0k, const float* __restrict__ c0v)
{
    int f4 = blockIdx.x * 256 + threadIdx.x;
    if (f4 >= NF4_TOT) return;
    const float* src;
    uint32_t* dst;
    int off;
    if (f4 < NF4_HID) {
        src = hidden; dst = g_hidh; off = f4;
    } else if (f4 < NF4_HID + NF4_W) {
        int w = f4 - NF4_HID;
        int sel = w / (NF4_W / 3);
        off = w - sel * (NF4_W / 3);
        src = (sel == 0) ? Wq : (sel == 1) ? Wk : Wv;
        dst = g_wh + (size_t)sel * (768 * 384);
    } else if (f4 < NF4_HID + NF4_W + NF4_C0) {
        off = f4 - NF4_HID - NF4_W; src = c0k; dst = g_c0kh;
    } else {
        off = f4 - NF4_HID - NF4_W - NF4_C0; src = c0v; dst = g_c0vh;
    }
    float4 v = ((const float4*)src)[off];
    ((uint2*)dst)[off] = make_uint2(packh2(v.x, v.y), packh2(v.z, v.w));
}

// ===========================================================================
// Kernel 1: QKV projection, fp16 m16n8k16 + ldmatrix, cp.async double buffer.
// 128x128 CTA tile, BK=64 (4 k16 groups), 256 thr (8 warps, 64x32).
// Per chunk: wait0 -> sync -> issue(i+1, alt buf) -> compute(i). One sync.
// ===========================================================================
#define QW 36                 // 32 data u32 + 4 pad: ldmatrix conflict-free
#define QBUF (128 * QW)       // u32 per matrix per buffer
#define QKV_SMEM (4 * QBUF * 4)   // 2 bufs x (A+B) = 73728 B (dynamic)

__global__ __launch_bounds__(256, 2) void qkv_mma_kernel(
    const float* __restrict__ bq, const float* __restrict__ bk,
    const float* __restrict__ bv,
    float* __restrict__ kout, float* __restrict__ vout)
{
    extern __shared__ uint32_t dsm[];   // [buf][A|B][QBUF]

    const int tid = threadIdx.x, lane = tid & 31, warp = tid >> 5;
    const int gid = lane >> 2, tig = lane & 3;
    const int nt = blockIdx.x, mt = blockIdx.y, sel = blockIdx.z;

    const uint32_t* Wsrc = g_wh + (size_t)sel * (768 * 384);
    const float* bias = (sel == 0) ? bq : (sel == 1) ? bk : bv;
    float* dst        = (sel == 1) ? kout : vout;
    uint32_t* hdst    = (sel == 0) ? g_qh : (sel == 1) ? g_kh : g_vh;

    const int m0 = mt * 128, n0 = nt * 128;
    const int wm = (warp >> 2) * 64, wn = (warp & 3) * 32;

    const uint32_t dsmu = smem_u32(dsm);
    const int arow = ((lane >> 3) & 1) * 8 + (lane & 7);
    const int acol = (lane >> 4) * 4;
    const int brow = (lane >> 4) * 8 + (lane & 7);
    const int bcol = ((lane >> 3) & 1) * 4;

    // copy coords: idx = p*256+tid -> row idx>>3, 16B group idx&7
    const int crow = tid >> 3, cc4 = tid & 7;

    float acc[4][4][4];
#pragma unroll
    for (int mi = 0; mi < 4; mi++)
#pragma unroll
        for (int ni = 0; ni < 4; ni++)
#pragma unroll
            for (int j = 0; j < 4; j++) acc[mi][ni][j] = 0.f;

    // prologue: issue chunk 0 into buf 0
#pragma unroll
    for (int p = 0; p < 4; p++) {
        int row = crow + p * 32;
        uint32_t so = (uint32_t)((row * QW + cc4 * 4) * 4);
        CP_ASYNC16(dsmu + so, g_hidh + (size_t)(m0 + row) * 384 + cc4 * 4);
        CP_ASYNC16(dsmu + (uint32_t)(QBUF * 4) + so,
                   Wsrc + (size_t)(n0 + row) * 384 + cc4 * 4);
    }
    CP_COMMIT();

    for (int i = 0; i < 12; i++) {
        CP_WAIT0();
        __syncthreads();
        // issue chunk i+1 into the other buffer (overlaps compute below)
        if (i + 1 < 12) {
            const int k0u = (i + 1) * 32;
            const uint32_t ab = dsmu + (uint32_t)(((i + 1) & 1) * 2 * QBUF * 4);
#pragma unroll
            for (int p = 0; p < 4; p++) {
                int row = crow + p * 32;
                uint32_t so = (uint32_t)((row * QW + cc4 * 4) * 4);
                CP_ASYNC16(ab + so,
                           g_hidh + (size_t)(m0 + row) * 384 + k0u + cc4 * 4);
                CP_ASYNC16(ab + (uint32_t)(QBUF * 4) + so,
                           Wsrc + (size_t)(n0 + row) * 384 + k0u + cc4 * 4);
            }
            CP_COMMIT();
        }

        // compute chunk i
        const uint32_t sAb = dsmu + (uint32_t)((i & 1) * 2 * QBUF * 4);
        const uint32_t sBb = sAb + (uint32_t)(QBUF * 4);
#pragma unroll
        for (int kg = 0; kg < 4; kg++) {
            uint32_t a[4][4], bf[4][2];
#pragma unroll
            for (int mi = 0; mi < 4; mi++) {
                uint32_t addr = sAb + (uint32_t)(((wm + mi * 16 + arow) * QW
                                                  + kg * 8 + acol) * 4);
                ldsm4(a[mi], addr);
            }
#pragma unroll
            for (int j = 0; j < 2; j++) {
                uint32_t d[4];
                uint32_t addr = sBb + (uint32_t)(((wn + j * 16 + brow) * QW
                                                  + kg * 8 + bcol) * 4);
                ldsm4(d, addr);
                bf[2*j][0]   = d[0]; bf[2*j][1]   = d[1];
                bf[2*j+1][0] = d[2]; bf[2*j+1][1] = d[3];
            }
#pragma unroll
            for (int mi = 0; mi < 4; mi++)
#pragma unroll
                for (int ni = 0; ni < 4; ni++)
                    mma16(acc[mi][ni], a[mi], bf[ni]);
        }
    }

    // epilogue: bias + fp32 k/v outputs + fp16 scratch copies
#pragma unroll
    for (int ni = 0; ni < 4; ni++) {
        int gn = n0 + wn + ni * 8 + 2 * tig;
        float b0 = __ldg(bias + gn), b1 = __ldg(bias + gn + 1);
        int hh = gn >> 6, dd = gn & 63;
#pragma unroll
        for (int mi = 0; mi < 4; mi++) {
#pragma unroll
            for (int rr = 0; rr < 2; rr++) {
                int gm = m0 + wm + mi * 16 + gid + rr * 8;
                float x0 = acc[mi][ni][2*rr]   + b0;
                float x1 = acc[mi][ni][2*rr+1] + b1;
                int bb = gm >> 6, ss = gm & 63;
                size_t base = ((size_t)bb * NH_ + hh) * S_ + ss;
                if (sel == 0) {
                    hdst[base * 32 + (dd >> 1)] = packh2(x0 * 0.125f, x1 * 0.125f);
                } else {
                    *(float2*)(dst + base * 64 + dd) = make_float2(x0, x1);
                    hdst[base * 32 + (dd >> 1)] = packh2(x0, x1);
                }
            }
        }
    }
}

// ===========================================================================
// Kernel 2: attention, fp16 m16n8k16 + ldmatrix(.trans) + online softmax.
// R14: double-buffered K/V/mask; seg0/seg2 tiles staged via cp.async
// (overlapping compute), seg1 (c1, fp32) staged synchronously. One
// __syncthreads per tile.
// ===========================================================================
#define KW 36   // 32 data u32 + 4 pad
#define KVB (32 * KW)

__global__ __launch_bounds__(128) void attn_mma_kernel(
    const float* __restrict__ c1k,  const float* __restrict__ c1v,
    const float* __restrict__ mask, float* __restrict__ out)
{
    __shared__ uint32_t qs[64 * KW];
    __shared__ uint32_t ks[2][KVB];
    __shared__ uint32_t vs[2][KVB];
    __shared__ float msm[2][32];

    const unsigned FULL = 0xffffffffu;
    const int bh = blockIdx.x, b = bh / NH_, h = bh % NH_;
    const int tid = threadIdx.x, lane = tid & 31, warp = tid >> 5;
    const int gid = lane >> 2, tig = lane & 3;

    const uint32_t ksu = smem_u32(&ks[0][0]), vsu = smem_u32(&vs[0][0]);
    const int krow = (lane >> 4) * 8 + (lane & 7);
    const int kcol = ((lane >> 3) & 1) * 4;
    const int vrow = ((lane >> 3) & 1) * 8 + (lane & 7);
    const int vcol = (lane >> 4) * 4;

    const float* maskb = mask + (size_t)b * LT_;
    const uint32_t* kh0 = g_c0kh + ((size_t)(b % BS_) * NH_ + h) * L0_ * 32;
    const uint32_t* vh0 = g_c0vh + ((size_t)(b % BS_) * NH_ + h) * L0_ * 32;
    const float*    kf1 = c1k + ((size_t)b * NH_ + h) * L1_ * HD_;
    const float*    vf1 = c1v + ((size_t)b * NH_ + h) * L1_ * HD_;
    const uint32_t* kh2 = g_kh + ((size_t)b * NH_ + h) * S_ * 32;
    const uint32_t* vh2 = g_vh + ((size_t)b * NH_ + h) * S_ * 32;

    // stage tile jj into buffer bi
    auto stage_tile = [&](int jj, int bi) {
        if (jj < 12 || jj >= 16) {
            const uint32_t* khs = (jj < 12) ? kh0 + (size_t)jj * 1024
                                            : kh2 + (size_t)(jj - 16) * 1024;
            const uint32_t* vhs = (jj < 12) ? vh0 + (size_t)jj * 1024
                                            : vh2 + (size_t)(jj - 16) * 1024;
            const uint32_t kdst = ksu + (uint32_t)(bi * KVB * 4);
            const uint32_t vdst = vsu + (uint32_t)(bi * KVB * 4);
#pragma unroll
            for (int p = 0; p < 2; p++) {
                int idx = p * 128 + tid;
                int row = idx >> 3, c4 = idx & 7;
                uint32_t so = (uint32_t)((row * KW + c4 * 4) * 4);
                CP_ASYNC16(kdst + so, khs + idx * 4);
                CP_ASYNC16(vdst + so, vhs + idx * 4);
            }
            CP_COMMIT();
        } else {
            const int t = (jj - 12) * 32;
#pragma unroll
            for (int p = 0; p < 4; p++) {
                int idx = p * 128 + tid;
                int r = idx >> 4, c4 = idx & 15;
                float4 kv = *(const float4*)(kf1 + (size_t)(t + r) * HD_ + c4 * 4);
                *(uint2*)&ks[bi][r * KW + c4 * 2] =
                    make_uint2(packh2(kv.x, kv.y), packh2(kv.z, kv.w));
                float4 vv = *(const float4*)(vf1 + (size_t)(t + r) * HD_ + c4 * 4);
                *(uint2*)&vs[bi][r * KW + c4 * 2] =
                    make_uint2(packh2(vv.x, vv.y), packh2(vv.z, vv.w));
            }
        }
        if (tid < 32) msm[bi][tid] = maskb[jj * 32 + tid];
    };

    // stage Q (fp16 scratch, pre-scaled) + tile 0
    {
        const uint4* qsrc = (const uint4*)(g_qh + (size_t)bh * 2048);
#pragma unroll
        for (int p = 0; p < 4; p++) {
            int idx = p * 128 + tid;
            int row = idx >> 3, c4 = idx & 7;
            *(uint4*)&qs[row * KW + c4 * 4] = qsrc[idx];
        }
    }
    stage_tile(0, 0);
    __syncthreads();

    uint32_t qf[4][4];
    {
        const int r = warp * 16 + gid;
#pragma unroll
        for (int kk = 0; kk < 4; kk++) {
            int c = kk * 8 + tig;
            qf[kk][0] = qs[r * KW + c];
            qf[kk][1] = qs[(r + 8) * KW + c];
            qf[kk][2] = qs[r * KW + c + 4];
            qf[kk][3] = qs[(r + 8) * KW + c + 4];
        }
    }

    float o[8][4];
#pragma unroll
    for (int nd = 0; nd < 8; nd++)
#pragma unroll
        for (int j = 0; j < 4; j++) o[nd][j] = 0.f;
    float m0 = -1e30f, m1 = -1e30f, l0 = 0.f, l1 = 0.f;

    for (int j = 0; j < 18; j++) {
        const int bi = j & 1;
        CP_WAIT0();
        __syncthreads();
        if (j + 1 < 18) stage_tile(j + 1, bi ^ 1);

        const uint32_t ksb = ksu + (uint32_t)(bi * KVB * 4);
        const uint32_t vsb = vsu + (uint32_t)(bi * KVB * 4);
        const float* msb = &msm[bi][0];

        // scores
        float sc[4][4];
#pragma unroll
        for (int nb = 0; nb < 4; nb++)
            sc[nb][0] = sc[nb][1] = sc[nb][2] = sc[nb][3] = 0.f;
#pragma unroll
        for (int kk = 0; kk < 4; kk++) {
#pragma unroll
            for (int nbp = 0; nbp < 2; nbp++) {
                uint32_t d[4];
                uint32_t addr = ksb + (uint32_t)(((nbp * 16 + krow) * KW
                                                  + kk * 8 + kcol) * 4);
                ldsm4(d, addr);
                mma16(sc[2*nbp],     qf[kk], &d[0]);
                mma16(sc[2*nbp + 1], qf[kk], &d[2]);
            }
        }
#pragma unroll
        for (int nb = 0; nb < 4; nb++) {
            float mk0 = msb[nb * 8 + 2 * tig], mk1 = msb[nb * 8 + 2 * tig + 1];
            sc[nb][0] += mk0; sc[nb][1] += mk1;
            sc[nb][2] += mk0; sc[nb][3] += mk1;
        }

        // online softmax
        float tm0 = -1e30f, tm1 = -1e30f;
#pragma unroll
        for (int nb = 0; nb < 4; nb++) {
            tm0 = fmaxf(tm0, fmaxf(sc[nb][0], sc[nb][1]));
            tm1 = fmaxf(tm1, fmaxf(sc[nb][2], sc[nb][3]));
        }
        tm0 = fmaxf(tm0, __shfl_xor_sync(FULL, tm0, 1));
        tm0 = fmaxf(tm0, __shfl_xor_sync(FULL, tm0, 2));
        tm1 = fmaxf(tm1, __shfl_xor_sync(FULL, tm1, 1));
        tm1 = fmaxf(tm1, __shfl_xor_sync(FULL, tm1, 2));
        float nm0 = fmaxf(m0, tm0), nm1 = fmaxf(m1, tm1);
        float cr0 = __expf(m0 - nm0), cr1 = __expf(m1 - nm1);
        m0 = nm0; m1 = nm1;
        l0 *= cr0; l1 *= cr1;

        uint32_t pa[2][4];
#pragma unroll
        for (int kc = 0; kc < 2; kc++) {
            float p00 = __expf(sc[2*kc][0]   - m0), p01 = __expf(sc[2*kc][1]   - m0);
            float p02 = __expf(sc[2*kc][2]   - m1), p03 = __expf(sc[2*kc][3]   - m1);
            float p10 = __expf(sc[2*kc+1][0] - m0), p11 = __expf(sc[2*kc+1][1] - m0);
            float p12 = __expf(sc[2*kc+1][2] - m1), p13 = __expf(sc[2*kc+1][3] - m1);
            l0 += p00 + p01 + p10 + p11;
            l1 += p02 + p03 + p12 + p13;
            pa[kc][0] = packh2(p00, p01);
            pa[kc][1] = packh2(p02, p03);
            pa[kc][2] = packh2(p10, p11);
            pa[kc][3] = packh2(p12, p13);
        }
#pragma unroll
        for (int nd = 0; nd < 8; nd++) {
            o[nd][0] *= cr0; o[nd][1] *= cr0;
            o[nd][2] *= cr1; o[nd][3] *= cr1;
        }

        // P @ V via ldmatrix.trans
#pragma unroll
        for (int kc = 0; kc < 2; kc++) {
#pragma unroll
            for (int ndp = 0; ndp < 4; ndp++) {
                uint32_t d[4];
                uint32_t addr = vsb + (uint32_t)(((kc * 16 + vrow) * KW
                                                  + ndp * 8 + vcol) * 4);
                ldsm4t(d, addr);
                mma16(o[2*ndp],     pa[kc], &d[0]);
                mma16(o[2*ndp + 1], pa[kc], &d[2]);
            }
        }
    }

    l0 += __shfl_xor_sync(FULL, l0, 1);
    l0 += __shfl_xor_sync(FULL, l0, 2);
    l1 += __shfl_xor_sync(FULL, l1, 1);
    l1 += __shfl_xor_sync(FULL, l1, 2);
    float i0 = 1.f / l0, i1 = 1.f / l1;

    const int s = warp * 16 + gid;
    float* ob  = out + ((size_t)b * S_ + s) * H_ + h * HD_;
    float* ob2 = out + ((size_t)b * S_ + s + 8) * H_ + h * HD_;
#pragma unroll
    for (int nd = 0; nd < 8; nd++) {
        int d = nd * 8 + 2 * tig;
        float2 v0 = { o[nd][0] * i0, o[nd][1] * i0 };
        float2 v1 = { o[nd][2] * i1, o[nd][3] * i1 };
        *(float2*)(ob + d)  = v0;
        *(float2*)(ob2 + d) = v1;
    }
}

// ---------------------------------------------------------------------------
extern "C" void kernel_launch(void* const* d_in, const int* in_sizes, int n_in,
                              void* d_out, int out_size)
{
    const float* hidden = (const float*)d_in[0];
    const float* mask   = (const float*)d_in[1];
    const float* Wq     = (const float*)d_in[2];
    const float* bq     = (const float*)d_in[3];
    const float* Wk     = (const float*)d_in[4];
    const float* bk     = (const float*)d_in[5];
    const float* Wv     = (const float*)d_in[6];
    const float* bv     = (const float*)d_in[7];
    const float* c0k    = (const float*)d_in[8];
    const float* c0v    = (const float*)d_in[9];
    const float* c1k    = (const float*)d_in[10];
    const float* c1v    = (const float*)d_in[11];

    float* out  = (float*)d_out;
    float* kout = out + (size_t)OUTSZ;
    float* vout = out + (size_t)2 * OUTSZ;

    cudaFuncSetAttribute(qkv_mma_kernel,
                         cudaFuncAttributeMaxDynamicSharedMemorySize, QKV_SMEM);

    prepack_kernel<<<(NF4_TOT + 255) / 256, 256>>>(hidden, Wq, Wk, Wv, c0k, c0v);

    dim3 g1(6, 120, 3);
    qkv_mma_kernel<<<g1, 256, QKV_SMEM>>>(bq, bk, bv, kout, vout);

    attn_mma_kernel<<<B_ * NH_, 128>>>(c1k, c1v, mask, out);
}

// round 16
// speedup vs baseline: 1.8080x; 1.0167x over previous
#include <cuda_runtime.h>
#include <cuda_fp16.h>
#include <cstdint>

// Problem constants (fixed shapes)
#define B_    240
#define S_    64
#define H_    768
#define NH_   12
#define HD_   64
#define L0_   384
#define L1_   128
#define LT_   576          // L0+L1+S
#define BS_   8            // cache0 batch = 240/30
#define OUTSZ (B_*S_*H_)   // 11796480
#define LOG2E 1.4426950408889634f

// fp16-packed scratch (u32 = half2 pair along the inner dim)
__device__ uint32_t g_hidh[15360 * 384];            // hidden
__device__ uint32_t g_wh[3 * 768 * 384];            // Wq|Wk|Wv
__device__ uint32_t g_c0kh[BS_ * NH_ * L0_ * 32];   // cache0 K
__device__ uint32_t g_c0vh[BS_ * NH_ * L0_ * 32];   // cache0 V
__device__ uint32_t g_qh[B_ * NH_ * S_ * 32];       // q (pre-scaled by log2e/8)
__device__ uint32_t g_kh[B_ * NH_ * S_ * 32];       // k fp16 copy
__device__ uint32_t g_vh[B_ * NH_ * S_ * 32];       // v fp16 copy

// ---------------------------------------------------------------------------
// helpers
// ---------------------------------------------------------------------------
__device__ __forceinline__ uint32_t packh2(float lo, float hi) {
    __half2 h = __floats2half2_rn(lo, hi);
    return *reinterpret_cast<uint32_t*>(&h);
}
__device__ __forceinline__ float ex2(float x) {
    float r;
    asm("ex2.approx.f32 %0, %1;" : "=f"(r) : "f"(x));
    return r;
}
__device__ __forceinline__ uint32_t smem_u32(const void* p) {
    uint32_t a;
    asm("{ .reg .u64 t; cvta.to.shared.u64 t, %1; cvt.u32.u64 %0, t; }"
        : "=r"(a) : "l"(p));
    return a;
}
__device__ __forceinline__ void mma16(float* d, const uint32_t* a, const uint32_t* b) {
    asm volatile(
        "mma.sync.aligned.m16n8k16.row.col.f32.f16.f16.f32 "
        "{%0,%1,%2,%3}, {%4,%5,%6,%7}, {%8,%9}, {%0,%1,%2,%3};"
        : "+f"(d[0]), "+f"(d[1]), "+f"(d[2]), "+f"(d[3])
        : "r"(a[0]), "r"(a[1]), "r"(a[2]), "r"(a[3]), "r"(b[0]), "r"(b[1]));
}
__device__ __forceinline__ void ldsm4(uint32_t* d, uint32_t addr) {
    asm volatile("ldmatrix.sync.aligned.m8n8.x4.shared.b16 {%0,%1,%2,%3}, [%4];"
        : "=r"(d[0]), "=r"(d[1]), "=r"(d[2]), "=r"(d[3]) : "r"(addr));
}
__device__ __forceinline__ void ldsm4t(uint32_t* d, uint32_t addr) {
    asm volatile("ldmatrix.sync.aligned.m8n8.x4.trans.shared.b16 {%0,%1,%2,%3}, [%4];"
        : "=r"(d[0]), "=r"(d[1]), "=r"(d[2]), "=r"(d[3]) : "r"(addr));
}
#define CP_ASYNC16(saddr, gaddr) \
    asm volatile("cp.async.cg.shared.global [%0], [%1], 16;" \
                 :: "r"(saddr), "l"(gaddr))
#define CP_COMMIT()  asm volatile("cp.async.commit_group;")
#define CP_WAIT0()   asm volatile("cp.async.wait_group 0;")

// ===========================================================================
// Kernel 0: prepack fp32 -> packed fp16 (hidden, W, c0k, c0v)
// ===========================================================================
#define NF4_HID 2949120
#define NF4_W   442368
#define NF4_C0  589824
#define NF4_TOT (NF4_HID + NF4_W + 2 * NF4_C0)

__global__ __launch_bounds__(256) void prepack_kernel(
    const float* __restrict__ hidden,
    const float* __restrict__ Wq, const float* __restrict__ Wk,
    const float* __restrict__ Wv,
    const float* __restrict__ c0k, const float* __restrict__ c0v)
{
    int f4 = blockIdx.x * 256 + threadIdx.x;
    if (f4 >= NF4_TOT) return;
    const float* src;
    uint32_t* dst;
    int off;
    if (f4 < NF4_HID) {
        src = hidden; dst = g_hidh; off = f4;
    } else if (f4 < NF4_HID + NF4_W) {
        int w = f4 - NF4_HID;
        int sel = w / (NF4_W / 3);
        off = w - sel * (NF4_W / 3);
        src = (sel == 0) ? Wq : (sel == 1) ? Wk : Wv;
        dst = g_wh + (size_t)sel * (768 * 384);
    } else if (f4 < NF4_HID + NF4_W + NF4_C0) {
        off = f4 - NF4_HID - NF4_W; src = c0k; dst = g_c0kh;
    } else {
        off = f4 - NF4_HID - NF4_W - NF4_C0; src = c0v; dst = g_c0vh;
    }
    float4 v = ((const float4*)src)[off];
    ((uint2*)dst)[off] = make_uint2(packh2(v.x, v.y), packh2(v.z, v.w));
}

// ===========================================================================
// Kernel 1: QKV projection, fp16 m16n8k16 + ldmatrix, cp.async double buffer.
// (R14 structure; only change: q prescale constant folds log2e)
// ===========================================================================
#define QW 36
#define QBUF (128 * QW)
#define QKV_SMEM (4 * QBUF * 4)

__global__ __launch_bounds__(256, 2) void qkv_mma_kernel(
    const float* __restrict__ bq, const float* __restrict__ bk,
    const float* __restrict__ bv,
    float* __restrict__ kout, float* __restrict__ vout)
{
    extern __shared__ uint32_t dsm[];

    const int tid = threadIdx.x, lane = tid & 31, warp = tid >> 5;
    const int gid = lane >> 2, tig = lane & 3;
    const int nt = blockIdx.x, mt = blockIdx.y, sel = blockIdx.z;

    const uint32_t* Wsrc = g_wh + (size_t)sel * (768 * 384);
    const float* bias = (sel == 0) ? bq : (sel == 1) ? bk : bv;
    float* dst        = (sel == 1) ? kout : vout;
    uint32_t* hdst    = (sel == 0) ? g_qh : (sel == 1) ? g_kh : g_vh;

    const int m0 = mt * 128, n0 = nt * 128;
    const int wm = (warp >> 2) * 64, wn = (warp & 3) * 32;

    const uint32_t dsmu = smem_u32(dsm);
    const int arow = ((lane >> 3) & 1) * 8 + (lane & 7);
    const int acol = (lane >> 4) * 4;
    const int brow = (lane >> 4) * 8 + (lane & 7);
    const int bcol = ((lane >> 3) & 1) * 4;
    const int crow = tid >> 3, cc4 = tid & 7;

    float acc[4][4][4];
#pragma unroll
    for (int mi = 0; mi < 4; mi++)
#pragma unroll
        for (int ni = 0; ni < 4; ni++)
#pragma unroll
            for (int j = 0; j < 4; j++) acc[mi][ni][j] = 0.f;

#pragma unroll
    for (int p = 0; p < 4; p++) {
        int row = crow + p * 32;
        uint32_t so = (uint32_t)((row * QW + cc4 * 4) * 4);
        CP_ASYNC16(dsmu + so, g_hidh + (size_t)(m0 + row) * 384 + cc4 * 4);
        CP_ASYNC16(dsmu + (uint32_t)(QBUF * 4) + so,
                   Wsrc + (size_t)(n0 + row) * 384 + cc4 * 4);
    }
    CP_COMMIT();

    for (int i = 0; i < 12; i++) {
        CP_WAIT0();
        __syncthreads();
        if (i + 1 < 12) {
            const int k0u = (i + 1) * 32;
            const uint32_t ab = dsmu + (uint32_t)(((i + 1) & 1) * 2 * QBUF * 4);
#pragma unroll
            for (int p = 0; p < 4; p++) {
                int row = crow + p * 32;
                uint32_t so = (uint32_t)((row * QW + cc4 * 4) * 4);
                CP_ASYNC16(ab + so,
                           g_hidh + (size_t)(m0 + row) * 384 + k0u + cc4 * 4);
                CP_ASYNC16(ab + (uint32_t)(QBUF * 4) + so,
                           Wsrc + (size_t)(n0 + row) * 384 + k0u + cc4 * 4);
            }
            CP_COMMIT();
        }

        const uint32_t sAb = dsmu + (uint32_t)((i & 1) * 2 * QBUF * 4);
        const uint32_t sBb = sAb + (uint32_t)(QBUF * 4);
#pragma unroll
        for (int kg = 0; kg < 4; kg++) {
            uint32_t a[4][4], bf[4][2];
#pragma unroll
            for (int mi = 0; mi < 4; mi++) {
                uint32_t addr = sAb + (uint32_t)(((wm + mi * 16 + arow) * QW
                                                  + kg * 8 + acol) * 4);
                ldsm4(a[mi], addr);
            }
#pragma unroll
            for (int j = 0; j < 2; j++) {
                uint32_t d[4];
                uint32_t addr = sBb + (uint32_t)(((wn + j * 16 + brow) * QW
                                                  + kg * 8 + bcol) * 4);
                ldsm4(d, addr);
                bf[2*j][0]   = d[0]; bf[2*j][1]   = d[1];
                bf[2*j+1][0] = d[2]; bf[2*j+1][1] = d[3];
            }
#pragma unroll
            for (int mi = 0; mi < 4; mi++)
#pragma unroll
                for (int ni = 0; ni < 4; ni++)
                    mma16(acc[mi][ni], a[mi], bf[ni]);
        }
    }

    // epilogue: bias + fp32 k/v outputs + fp16 scratch copies
    const float qscale = 0.125f * LOG2E;
#pragma unroll
    for (int ni = 0; ni < 4; ni++) {
        int gn = n0 + wn + ni * 8 + 2 * tig;
        float b0 = __ldg(bias + gn), b1 = __ldg(bias + gn + 1);
        int hh = gn >> 6, dd = gn & 63;
#pragma unroll
        for (int mi = 0; mi < 4; mi++) {
#pragma unroll
            for (int rr = 0; rr < 2; rr++) {
                int gm = m0 + wm + mi * 16 + gid + rr * 8;
                float x0 = acc[mi][ni][2*rr]   + b0;
                float x1 = acc[mi][ni][2*rr+1] + b1;
                int bb = gm >> 6, ss = gm & 63;
                size_t base = ((size_t)bb * NH_ + hh) * S_ + ss;
                if (sel == 0) {
                    hdst[base * 32 + (dd >> 1)] = packh2(x0 * qscale, x1 * qscale);
                } else {
                    *(float2*)(dst + base * 64 + dd) = make_float2(x0, x1);
                    hdst[base * 32 + (dd >> 1)] = packh2(x0, x1);
                }
            }
        }
    }
}

// ===========================================================================
// Kernel 2: attention, fp16 m16n8k16 + ldmatrix(.trans), exp2 softmax.
// R15: no qf register cache (Q frags via ldmatrix per tile), pa inlined,
// __launch_bounds__(128,5) for 5 CTAs/SM. cp.async double buffer kept.
// Scores are in log2-domain (q pre-scaled by log2e/8, mask scaled at load).
// ===========================================================================
#define KW 36
#define KVB (32 * KW)

__global__ __launch_bounds__(128, 5) void attn_mma_kernel(
    const float* __restrict__ c1k,  const float* __restrict__ c1v,
    const float* __restrict__ mask, float* __restrict__ out)
{
    __shared__ uint32_t qs[64 * KW];
    __shared__ uint32_t ks[2][KVB];
    __shared__ uint32_t vs[2][KVB];
    __shared__ float msm[2][32];

    const unsigned FULL = 0xffffffffu;
    const int bh = blockIdx.x, b = bh / NH_, h = bh % NH_;
    const int tid = threadIdx.x, lane = tid & 31, warp = tid >> 5;
    const int gid = lane >> 2, tig = lane & 3;

    const uint32_t qsu = smem_u32(qs);
    const uint32_t ksu = smem_u32(&ks[0][0]), vsu = smem_u32(&vs[0][0]);
    const int arow = ((lane >> 3) & 1) * 8 + (lane & 7);   // Q A-frag rows
    const int acol = (lane >> 4) * 4;
    const int krow = (lane >> 4) * 8 + (lane & 7);
    const int kcol = ((lane >> 3) & 1) * 4;
    const int vrow = ((lane >> 3) & 1) * 8 + (lane & 7);
    const int vcol = (lane >> 4) * 4;

    const float* maskb = mask + (size_t)b * LT_;
    const uint32_t* kh0 = g_c0kh + ((size_t)(b % BS_) * NH_ + h) * L0_ * 32;
    const uint32_t* vh0 = g_c0vh + ((size_t)(b % BS_) * NH_ + h) * L0_ * 32;
    const float*    kf1 = c1k + ((size_t)b * NH_ + h) * L1_ * HD_;
    const float*    vf1 = c1v + ((size_t)b * NH_ + h) * L1_ * HD_;
    const uint32_t* kh2 = g_kh + ((size_t)b * NH_ + h) * S_ * 32;
    const uint32_t* vh2 = g_vh + ((size_t)b * NH_ + h) * S_ * 32;

    auto stage_tile = [&](int jj, int bi) {
        if (jj < 12 || jj >= 16) {
            const uint32_t* khs = (jj < 12) ? kh0 + (size_t)jj * 1024
                                            : kh2 + (size_t)(jj - 16) * 1024;
            const uint32_t* vhs = (jj < 12) ? vh0 + (size_t)jj * 1024
                                            : vh2 + (size_t)(jj - 16) * 1024;
            const uint32_t kdst = ksu + (uint32_t)(bi * KVB * 4);
            const uint32_t vdst = vsu + (uint32_t)(bi * KVB * 4);
#pragma unroll
            for (int p = 0; p < 2; p++) {
                int idx = p * 128 + tid;
                int row = idx >> 3, c4 = idx & 7;
                uint32_t so = (uint32_t)((row * KW + c4 * 4) * 4);
                CP_ASYNC16(kdst + so, khs + idx * 4);
                CP_ASYNC16(vdst + so, vhs + idx * 4);
            }
            CP_COMMIT();
        } else {
            const int t = (jj - 12) * 32;
#pragma unroll
            for (int p = 0; p < 4; p++) {
                int idx = p * 128 + tid;
                int r = idx >> 4, c4 = idx & 15;
                float4 kv = *(const float4*)(kf1 + (size_t)(t + r) * HD_ + c4 * 4);
                *(uint2*)&ks[bi][r * KW + c4 * 2] =
                    make_uint2(packh2(kv.x, kv.y), packh2(kv.z, kv.w));
                float4 vv = *(const float4*)(vf1 + (size_t)(t + r) * HD_ + c4 * 4);
                *(uint2*)&vs[bi][r * KW + c4 * 2] =
                    make_uint2(packh2(vv.x, vv.y), packh2(vv.z, vv.w));
            }
        }
        if (tid < 32) msm[bi][tid] = maskb[jj * 32 + tid] * LOG2E;
    };

    // stage Q (fp16 scratch, pre-scaled by log2e/8) + tile 0
    {
        const uint4* qsrc = (const uint4*)(g_qh + (size_t)bh * 2048);
#pragma unroll
        for (int p = 0; p < 4; p++) {
            int idx = p * 128 + tid;
            int row = idx >> 3, c4 = idx & 7;
            *(uint4*)&qs[row * KW + c4 * 4] = qsrc[idx];
        }
    }
    stage_tile(0, 0);
    __syncthreads();

    float o[8][4];
#pragma unroll
    for (int nd = 0; nd < 8; nd++)
#pragma unroll
        for (int j = 0; j < 4; j++) o[nd][j] = 0.f;
    float m0 = -1e30f, m1 = -1e30f, l0 = 0.f, l1 = 0.f;

    for (int j = 0; j < 18; j++) {
        const int bi = j & 1;
        CP_WAIT0();
        __syncthreads();
        if (j + 1 < 18) stage_tile(j + 1, bi ^ 1);

        const uint32_t ksb = ksu + (uint32_t)(bi * KVB * 4);
        const uint32_t vsb = vsu + (uint32_t)(bi * KVB * 4);
        const float* msb = &msm[bi][0];

        // scores (log2 domain)
        float sc[4][4];
#pragma unroll
        for (int nb = 0; nb < 4; nb++)
            sc[nb][0] = sc[nb][1] = sc[nb][2] = sc[nb][3] = 0.f;
#pragma unroll
        for (int kk = 0; kk < 4; kk++) {
            uint32_t qa[4];
            ldsm4(qa, qsu + (uint32_t)(((warp * 16 + arow) * KW
                                        + kk * 8 + acol) * 4));
#pragma unroll
            for (int nbp = 0; nbp < 2; nbp++) {
                uint32_t d[4];
                uint32_t addr = ksb + (uint32_t)(((nbp * 16 + krow) * KW
                                                  + kk * 8 + kcol) * 4);
                ldsm4(d, addr);
                mma16(sc[2*nbp],     qa, &d[0]);
                mma16(sc[2*nbp + 1], qa, &d[2]);
            }
        }
#pragma unroll
        for (int nb = 0; nb < 4; nb++) {
            float mk0 = msb[nb * 8 + 2 * tig], mk1 = msb[nb * 8 + 2 * tig + 1];
            sc[nb][0] += mk0; sc[nb][1] += mk1;
            sc[nb][2] += mk0; sc[nb][3] += mk1;
        }

        // online softmax (base-2)
        float tm0 = -1e30f, tm1 = -1e30f;
#pragma unroll
        for (int nb = 0; nb < 4; nb++) {
            tm0 = fmaxf(tm0, fmaxf(sc[nb][0], sc[nb][1]));
            tm1 = fmaxf(tm1, fmaxf(sc[nb][2], sc[nb][3]));
        }
        tm0 = fmaxf(tm0, __shfl_xor_sync(FULL, tm0, 1));
        tm0 = fmaxf(tm0, __shfl_xor_sync(FULL, tm0, 2));
        tm1 = fmaxf(tm1, __shfl_xor_sync(FULL, tm1, 1));
        tm1 = fmaxf(tm1, __shfl_xor_sync(FULL, tm1, 2));
        float nm0 = fmaxf(m0, tm0), nm1 = fmaxf(m1, tm1);
        float cr0 = ex2(m0 - nm0), cr1 = ex2(m1 - nm1);
        m0 = nm0; m1 = nm1;
        l0 *= cr0; l1 *= cr1;
#pragma unroll
        for (int nd = 0; nd < 8; nd++) {
            o[nd][0] *= cr0; o[nd][1] *= cr0;
            o[nd][2] *= cr1; o[nd][3] *= cr1;
        }

        // exp2 + pack P per kc, then P @ V via ldmatrix.trans
#pragma unroll
        for (int kc = 0; kc < 2; kc++) {
            float p00 = ex2(sc[2*kc][0]   - m0), p01 = ex2(sc[2*kc][1]   - m0);
            float p02 = ex2(sc[2*kc][2]   - m1), p03 = ex2(sc[2*kc][3]   - m1);
            float p10 = ex2(sc[2*kc+1][0] - m0), p11 = ex2(sc[2*kc+1][1] - m0);
            float p12 = ex2(sc[2*kc+1][2] - m1), p13 = ex2(sc[2*kc+1][3] - m1);
            l0 += p00 + p01 + p10 + p11;
            l1 += p02 + p03 + p12 + p13;
            uint32_t pa[4];
            pa[0] = packh2(p00, p01);
            pa[1] = packh2(p02, p03);
            pa[2] = packh2(p10, p11);
            pa[3] = packh2(p12, p13);
#pragma unroll
            for (int ndp = 0; ndp < 4; ndp++) {
                uint32_t d[4];
                uint32_t addr = vsb + (uint32_t)(((kc * 16 + vrow) * KW
                                                  + ndp * 8 + vcol) * 4);
                ldsm4t(d, addr);
                mma16(o[2*ndp],     pa, &d[0]);
                mma16(o[2*ndp + 1], pa, &d[2]);
            }
        }
    }

    l0 += __shfl_xor_sync(FULL, l0, 1);
    l0 += __shfl_xor_sync(FULL, l0, 2);
    l1 += __shfl_xor_sync(FULL, l1, 1);
    l1 += __shfl_xor_sync(FULL, l1, 2);
    float i0 = 1.f / l0, i1 = 1.f / l1;

    const int s = warp * 16 + gid;
    float* ob  = out + ((size_t)b * S_ + s) * H_ + h * HD_;
    float* ob2 = out + ((size_t)b * S_ + s + 8) * H_ + h * HD_;
#pragma unroll
    for (int nd = 0; nd < 8; nd++) {
        int d = nd * 8 + 2 * tig;
        float2 v0 = { o[nd][0] * i0, o[nd][1] * i0 };
        float2 v1 = { o[nd][2] * i1, o[nd][3] * i1 };
        *(float2*)(ob + d)  = v0;
        *(float2*)(ob2 + d) = v1;
    }
}

// ---------------------------------------------------------------------------
extern "C" void kernel_launch(void* const* d_in, const int* in_sizes, int n_in,
                              void* d_out, int out_size)
{
    const float* hidden = (const float*)d_in[0];
    const float* mask   = (const float*)d_in[1];
    const float* Wq     = (const float*)d_in[2];
    const float* bq     = (const float*)d_in[3];
    const float* Wk     = (const float*)d_in[4];
    const float* bk     = (const float*)d_in[5];
    const float* Wv     = (const float*)d_in[6];
    const float* bv     = (const float*)d_in[7];
    const float* c0k    = (const float*)d_in[8];
    const float* c0v    = (const float*)d_in[9];
    const float* c1k    = (const float*)d_in[10];
    const float* c1v    = (const float*)d_in[11];

    float* out  = (float*)d_out;
    float* kout = out + (size_t)OUTSZ;
    float* vout = out + (size_t)2 * OUTSZ;

    cudaFuncSetAttribute(qkv_mma_kernel,
                         cudaFuncAttributeMaxDynamicSharedMemorySize, QKV_SMEM);

    prepack_kernel<<<(NF4_TOT + 255) / 256, 256>>>(hidden, Wq, Wk, Wv, c0k, c0v);

    dim3 g1(6, 120, 3);
    qkv_mma_kernel<<<g1, 256, QKV_SMEM>>>(bq, bk, bv, kout, vout);

    attn_mma_kernel<<<B_ * NH_, 128>>>(c1k, c1v, mask, out);
}